// round 5
// baseline (speedup 1.0000x reference)
#include <cuda_runtime.h>
#include <cuda_bf16.h>
#include <cstdint>
#include <math.h>

// Problem constants
#define BB 8
#define NN 2048
#define DD 256
#define SS 128
#define HH 512
#define EE 1152          // 2H + S
#define BNROWS (BB*NN)   // 16384
#define RSQRT_S 0.08838834764831845f  // 1/sqrt(128)

// ---- scratch (allocation-free rule: __device__ globals) ----
__device__ __nv_bfloat16 d_xhi[(size_t)BNROWS*DD];
__device__ __nv_bfloat16 d_xlo[(size_t)BNROWS*DD];
__device__ float d_u[(size_t)BNROWS*HH];
__device__ float d_v[(size_t)BNROWS*HH];
__device__ __nv_bfloat16 d_qhi[(size_t)BNROWS*SS];
__device__ __nv_bfloat16 d_qlo[(size_t)BNROWS*SS];
__device__ __nv_bfloat16 d_khi[(size_t)BNROWS*SS];
__device__ __nv_bfloat16 d_klo[(size_t)BNROWS*SS];
__device__ __nv_bfloat16 d_vThi[(size_t)BB*HH*NN];   // [b][h][m]
__device__ __nv_bfloat16 d_vTlo[(size_t)BB*HH*NN];
__device__ __nv_bfloat16 d_ahi[(size_t)BB*NN*NN];    // attn [b][n][m]
__device__ __nv_bfloat16 d_alo[(size_t)BB*NN*NN];
__device__ __nv_bfloat16 d_ghi[(size_t)BNROWS*HH];   // gated hi/lo
__device__ __nv_bfloat16 d_glo[(size_t)BNROWS*HH];
__device__ __nv_bfloat16 d_wuvThi[(size_t)EE*DD];    // W_uv^T [e][d]
__device__ __nv_bfloat16 d_wuvTlo[(size_t)EE*DD];
__device__ __nv_bfloat16 d_woThi[(size_t)DD*HH];     // W_o^T [d][h]
__device__ __nv_bfloat16 d_woTlo[(size_t)DD*HH];

// ============================================================
// Helpers
// ============================================================
__device__ __forceinline__ uint32_t smem_u32(const void* p) {
    uint32_t a;
    asm("{ .reg .u64 t; cvta.to.shared.u64 t, %1; cvt.u32.u64 %0, t; }"
        : "=r"(a) : "l"(p));
    return a;
}

#define LDSM_X4(r0, r1, r2, r3, addr) \
    asm volatile("ldmatrix.sync.aligned.m8n8.x4.shared.b16 {%0,%1,%2,%3}, [%4];" \
        : "=r"(r0), "=r"(r1), "=r"(r2), "=r"(r3) : "r"(addr))

#define MMA16816(d, a, b) \
    asm volatile("mma.sync.aligned.m16n8k16.row.col.f32.bf16.bf16.f32 " \
        "{%0,%1,%2,%3}, {%4,%5,%6,%7}, {%8,%9}, {%0,%1,%2,%3};" \
        : "+f"((d)[0]), "+f"((d)[1]), "+f"((d)[2]), "+f"((d)[3]) \
        : "r"((a)[0]), "r"((a)[1]), "r"((a)[2]), "r"((a)[3]), \
          "r"((b)[0]), "r"((b)[1]))

__device__ __forceinline__ void cp16(uint32_t dst, const __nv_bfloat16* src) {
    asm volatile("cp.async.cg.shared.global [%0], [%1], 16;"
        :: "r"(dst), "l"(src));
}
#define CP_COMMIT() asm volatile("cp.async.commit_group;" ::: "memory")
#define CP_WAIT2()  asm volatile("cp.async.wait_group 2;" ::: "memory")
#define CP_WAIT0()  asm volatile("cp.async.wait_group 0;" ::: "memory")

__device__ __forceinline__ void bf16split(float v, __nv_bfloat16& hi, __nv_bfloat16& lo) {
    hi = __float2bfloat16(v);
    lo = __float2bfloat16(v - __bfloat162float(hi));
}

// ============================================================
// HMMA GEMM core: BM=128, BN=64, BK=32, 256 threads, 2 CTAs/SM.
// A row-major [128][K], B n-major [64][K], hi/lo bf16, 3-term split.
// Stage = Ah 8K | Al 8K | Bh 4K | Bl 4K = 24KB, 4 stages (96KB).
// 64B rows; swizzle: granule gi ^= (row>>1)&3  (ldmatrix conflict-free).
// Pipeline: prefetch distance 3, wait_group 2, ONE syncthreads/iter.
// ============================================================
#define STAGE_BYTES 24576
#define NSTAGE 4
#define MMA_SMEM (NSTAGE*STAGE_BYTES)

// ROWS*4 granules of 16B, strided by 256 threads
template <int ROWS>
__device__ __forceinline__ void load_oper(uint32_t dstBase, const __nv_bfloat16* src,
                                          int ld, int kt, int tid) {
    #pragma unroll
    for (int j = 0; j < ROWS*4/256; j++) {
        int g = tid + j * 256;
        int row = g >> 2;
        int gi  = g & 3;
        int gis = gi ^ ((row >> 1) & 3);
        cp16(dstBase + row * 64 + gis * 16, src + (size_t)row * ld + kt + gi * 8);
    }
}

__device__ __forceinline__ void load_chunk(uint32_t sb, int stage,
        const __nv_bfloat16* Ah, const __nv_bfloat16* Al, int ldA,
        const __nv_bfloat16* Bh, const __nv_bfloat16* Bl, int ldB,
        int kt, int tid) {
    uint32_t st = sb + stage * STAGE_BYTES;
    load_oper<128>(st,         Ah, ldA, kt, tid);
    load_oper<128>(st +  8192, Al, ldA, kt, tid);
    load_oper<64> (st + 16384, Bh, ldB, kt, tid);
    load_oper<64> (st + 20480, Bl, ldB, kt, tid);
}

__device__ __forceinline__ void compute_chunk(uint32_t st, int lane, int wm, int wn,
                                              float acc[4][2][4]) {
    const uint32_t aH = st, aL = st + 8192, bH = st + 16384, bL = st + 20480;
    #pragma unroll
    for (int ks = 0; ks < 2; ks++) {
        uint32_t Ahf[4][4], Alf[4][4];
        #pragma unroll
        for (int mi = 0; mi < 4; mi++) {
            int row = wm * 64 + mi * 16 + (lane & 15);
            int gi  = ks * 2 + (lane >> 4);
            uint32_t off = row * 64 + ((gi ^ ((row >> 1) & 3)) * 16);
            LDSM_X4(Ahf[mi][0], Ahf[mi][1], Ahf[mi][2], Ahf[mi][3], aH + off);
            LDSM_X4(Alf[mi][0], Alf[mi][1], Alf[mi][2], Alf[mi][3], aL + off);
        }
        uint32_t Bhf[2][2], Blf[2][2];
        {
            int row = wn * 16 + (lane & 7) + ((lane >> 4) << 3);
            int gi  = ks * 2 + ((lane >> 3) & 1);
            uint32_t off = row * 64 + ((gi ^ ((row >> 1) & 3)) * 16);
            LDSM_X4(Bhf[0][0], Bhf[0][1], Bhf[1][0], Bhf[1][1], bH + off);
            LDSM_X4(Blf[0][0], Blf[0][1], Blf[1][0], Blf[1][1], bL + off);
        }
        #pragma unroll
        for (int mi = 0; mi < 4; mi++)
            #pragma unroll
            for (int ni = 0; ni < 2; ni++) {
                MMA16816(acc[mi][ni], Ahf[mi], Bhf[ni]);
                MMA16816(acc[mi][ni], Ahf[mi], Blf[ni]);
                MMA16816(acc[mi][ni], Alf[mi], Bhf[ni]);
            }
    }
}

template <class Epi>
__device__ __forceinline__ void mma_gemm_core(
        const __nv_bfloat16* Ah, const __nv_bfloat16* Al, int ldA,
        const __nv_bfloat16* Bh, const __nv_bfloat16* Bl, int ldB,
        int K, char* smem, Epi epi) {
    uint32_t sb = smem_u32(smem);
    int tid = threadIdx.x;
    int lane = tid & 31, warp = tid >> 5;
    int wm = warp & 1, wn = warp >> 1;

    float acc[4][2][4] = {};
    const int nc = K / 32;

    // prologue: stages 0..2
    #pragma unroll
    for (int i = 0; i < 3; i++) {
        if (i < nc) load_chunk(sb, i, Ah, Al, ldA, Bh, Bl, ldB, i * 32, tid);
        CP_COMMIT();
    }

    for (int c = 0; c < nc; c++) {
        CP_WAIT2();          // stage c resident (groups c+1, c+2 may be in flight)
        __syncthreads();     // all warps done with stage (c-1) & see stage c
        if (c + 3 < nc)
            load_chunk(sb, (c + 3) & (NSTAGE - 1), Ah, Al, ldA, Bh, Bl, ldB,
                       (c + 3) * 32, tid);
        CP_COMMIT();         // empty group at tail keeps counting uniform
        compute_chunk(sb + (c & (NSTAGE - 1)) * STAGE_BYTES, lane, wm, wn, acc);
    }

    #pragma unroll
    for (int mi = 0; mi < 4; mi++)
        #pragma unroll
        for (int ni = 0; ni < 2; ni++) {
            int r = wm * 64 + mi * 16 + (lane >> 2);
            int c = wn * 16 + ni * 8 + (lane & 3) * 2;
            epi(r,     c, acc[mi][ni][0], acc[mi][ni][1]);
            epi(r + 8, c, acc[mi][ni][2], acc[mi][ni][3]);
        }
}

// ============================================================
// prep: x -> normalized hi/lo bf16
// ============================================================
__global__ void prep_x_kernel(const float* __restrict__ x,
                              const float* __restrict__ g) {
    int row  = blockIdx.x * blockDim.y + threadIdx.y;
    int lane = threadIdx.x;
    const float4* xr = reinterpret_cast<const float4*>(x + (size_t)row * DD);
    float4 a = xr[lane];
    float4 b = xr[lane + 32];
    float s = a.x*a.x + a.y*a.y + a.z*a.z + a.w*a.w
            + b.x*b.x + b.y*b.y + b.z*b.z + b.w*b.w;
    #pragma unroll
    for (int off = 16; off; off >>= 1) s += __shfl_xor_sync(0xffffffffu, s, off);
    s = __shfl_sync(0xffffffffu, s, 0);
    float norm = sqrtf(s * (1.0f / DD));
    float scale = g[0] / fmaxf(norm, 1e-5f);

    float va[8] = {a.x, a.y, a.z, a.w, b.x, b.y, b.z, b.w};
    int idx[2] = {lane * 4, 128 + lane * 4};
    #pragma unroll
    for (int h = 0; h < 2; h++)
        #pragma unroll
        for (int j = 0; j < 4; j++) {
            float v = va[h*4 + j] * scale;
            __nv_bfloat16 hi, lo;
            bf16split(v, hi, lo);
            d_xhi[(size_t)row*DD + idx[h] + j] = hi;
            d_xlo[(size_t)row*DD + idx[h] + j] = lo;
        }
}

// ============================================================
// generic transpose + split:  in [R][C] fp32 -> out [C][R] bf16 hi/lo
// ============================================================
__global__ void transpose_split_kernel(const float* __restrict__ in,
                                       __nv_bfloat16* __restrict__ outh,
                                       __nv_bfloat16* __restrict__ outl,
                                       int R, int C) {
    __shared__ float t[32][33];
    size_t boff = (size_t)blockIdx.z * R * C;
    int c0 = blockIdx.x * 32, r0 = blockIdx.y * 32;
    int tx = threadIdx.x, ty = threadIdx.y;
    #pragma unroll
    for (int i = ty; i < 32; i += 8)
        t[i][tx] = in[boff + (size_t)(r0 + i) * C + c0 + tx];
    __syncthreads();
    #pragma unroll
    for (int i = ty; i < 32; i += 8) {
        float val = t[tx][i];   // = in[r0+tx][c0+i]
        __nv_bfloat16 hi, lo;
        bf16split(val, hi, lo);
        size_t idx = boff + (size_t)(c0 + i) * R + r0 + tx;
        outh[idx] = hi;
        outl[idx] = lo;
    }
}

// ============================================================
// Epilogues
// ============================================================
struct EpiUV {
    int rowBase, colBase;
    const float *buv, *gamma, *beta;
    __device__ void operator()(int r, int c, float v0, float v1) const {
        int row = rowBase + r;
        float vv[2] = {v0, v1};
        #pragma unroll
        for (int i = 0; i < 2; i++) {
            int col = colBase + c + i;
            float val = vv[i] + buv[col];
            val = val / (1.0f + __expf(-val));
            if (col < HH) {
                d_u[(size_t)row*HH + col] = val;
            } else if (col < 2*HH) {
                d_v[(size_t)row*HH + (col - HH)] = val;
            } else {
                int s = col - 2*HH;
                float vq = val * gamma[s]      + beta[s];
                float vk = val * gamma[SS + s] + beta[SS + s];
                size_t qi = (size_t)row*SS + s;
                __nv_bfloat16 hi, lo;
                bf16split(vq, hi, lo); d_qhi[qi] = hi; d_qlo[qi] = lo;
                bf16split(vk, hi, lo); d_khi[qi] = hi; d_klo[qi] = lo;
            }
        }
    }
};

struct EpiQK {
    size_t rowOff;   // b*NN + rowBase
    int colBase;
    __device__ void operator()(int r, int c, float v0, float v1) const {
        size_t idx = (rowOff + r) * NN + colBase + c;
        float a0 = fmaxf(v0 * RSQRT_S, 0.0f); a0 *= a0;
        float a1 = fmaxf(v1 * RSQRT_S, 0.0f); a1 *= a1;
        __nv_bfloat16 h0, l0, h1, l1;
        bf16split(a0, h0, l0);
        bf16split(a1, h1, l1);
        *reinterpret_cast<__nv_bfloat162*>(d_ahi + idx) = __nv_bfloat162{h0, h1};
        *reinterpret_cast<__nv_bfloat162*>(d_alo + idx) = __nv_bfloat162{l0, l1};
    }
};

struct EpiAV {
    size_t rowOff;   // b*NN + rowBase
    int colBase;
    __device__ void operator()(int r, int c, float v0, float v1) const {
        size_t rg = rowOff + r;
        size_t idx = rg * HH + colBase + c;
        float2 uu = *reinterpret_cast<const float2*>(d_u + idx);
        float g0 = uu.x * v0, g1 = uu.y * v1;
        __nv_bfloat16 h0, l0, h1, l1;
        bf16split(g0, h0, l0);
        bf16split(g1, h1, l1);
        *reinterpret_cast<__nv_bfloat162*>(d_ghi + idx) = __nv_bfloat162{h0, h1};
        *reinterpret_cast<__nv_bfloat162*>(d_glo + idx) = __nv_bfloat162{l0, l1};
    }
};

struct EpiO {
    int rowBase, colBase;
    const float* bo;
    float* out;
    __device__ void operator()(int r, int c, float v0, float v1) const {
        int row = rowBase + r;
        int col = colBase + c;
        float2 o = {v0 + bo[col], v1 + bo[col + 1]};
        *reinterpret_cast<float2*>(out + (size_t)row*DD + col) = o;
    }
};

// ============================================================
// GEMM kernels (BN=64 grids)
// ============================================================
__global__ void __launch_bounds__(256, 2)
k_uv(const float* __restrict__ buv, const float* __restrict__ gamma,
     const float* __restrict__ beta) {
    extern __shared__ char smem[];
    int rowBase = blockIdx.y * 128, colBase = blockIdx.x * 64;
    EpiUV epi{rowBase, colBase, buv, gamma, beta};
    mma_gemm_core(d_xhi + (size_t)rowBase * DD, d_xlo + (size_t)rowBase * DD, DD,
                  d_wuvThi + (size_t)colBase * DD, d_wuvTlo + (size_t)colBase * DD, DD,
                  DD, smem, epi);
}

__global__ void __launch_bounds__(256, 2)
k_qk() {
    extern __shared__ char smem[];
    int b = blockIdx.z, rowBase = blockIdx.y * 128, colBase = blockIdx.x * 64;
    size_t ra = (size_t)b * NN + rowBase;
    size_t rb = (size_t)b * NN + colBase;
    EpiQK epi{ra, colBase};
    mma_gemm_core(d_qhi + ra * SS, d_qlo + ra * SS, SS,
                  d_khi + rb * SS, d_klo + rb * SS, SS,
                  SS, smem, epi);
}

__global__ void __launch_bounds__(256, 2)
k_av() {
    extern __shared__ char smem[];
    int b = blockIdx.z, rowBase = blockIdx.y * 128, colBase = blockIdx.x * 64;
    size_t ra = (size_t)b * NN + rowBase;
    size_t hb = (size_t)b * HH + colBase;
    EpiAV epi{ra, colBase};
    mma_gemm_core(d_ahi + ra * NN, d_alo + ra * NN, NN,
                  d_vThi + hb * NN, d_vTlo + hb * NN, NN,
                  NN, smem, epi);
}

__global__ void __launch_bounds__(256, 2)
k_o(const float* __restrict__ bo, float* __restrict__ out) {
    extern __shared__ char smem[];
    int rowBase = blockIdx.y * 128, colBase = blockIdx.x * 64;
    EpiO epi{rowBase, colBase, bo, out};
    mma_gemm_core(d_ghi + (size_t)rowBase * HH, d_glo + (size_t)rowBase * HH, HH,
                  d_woThi + (size_t)colBase * HH, d_woTlo + (size_t)colBase * HH, HH,
                  HH, smem, epi);
}

// ============================================================
extern "C" void kernel_launch(void* const* d_in, const int* in_sizes, int n_in,
                              void* d_out, int out_size) {
    (void)in_sizes; (void)n_in; (void)out_size;
    const float* x     = (const float*)d_in[0];
    const float* g     = (const float*)d_in[1];
    const float* Wuv   = (const float*)d_in[2];
    const float* buv   = (const float*)d_in[3];
    const float* gamma = (const float*)d_in[4];
    const float* beta  = (const float*)d_in[5];
    const float* Wo    = (const float*)d_in[6];
    const float* bo    = (const float*)d_in[7];
    float* out = (float*)d_out;

    static int smem_set = 0;
    if (!smem_set) {
        cudaFuncSetAttribute(k_uv, cudaFuncAttributeMaxDynamicSharedMemorySize, MMA_SMEM);
        cudaFuncSetAttribute(k_qk, cudaFuncAttributeMaxDynamicSharedMemorySize, MMA_SMEM);
        cudaFuncSetAttribute(k_av, cudaFuncAttributeMaxDynamicSharedMemorySize, MMA_SMEM);
        cudaFuncSetAttribute(k_o,  cudaFuncAttributeMaxDynamicSharedMemorySize, MMA_SMEM);
        smem_set = 1;
    }

    prep_x_kernel<<<BNROWS/8, dim3(32, 8)>>>(x, g);

    {   // W_uv: [D=256][E=1152] -> [E][D]
        __nv_bfloat16 *th, *tl;
        cudaGetSymbolAddress((void**)&th, d_wuvThi);
        cudaGetSymbolAddress((void**)&tl, d_wuvTlo);
        transpose_split_kernel<<<dim3(EE/32, DD/32, 1), dim3(32, 8)>>>(Wuv, th, tl, DD, EE);
    }
    {   // W_o: [H=512][D=256] -> [D][H]
        __nv_bfloat16 *th, *tl;
        cudaGetSymbolAddress((void**)&th, d_woThi);
        cudaGetSymbolAddress((void**)&tl, d_woTlo);
        transpose_split_kernel<<<dim3(DD/32, HH/32, 1), dim3(32, 8)>>>(Wo, th, tl, HH, DD);
    }

    k_uv<<<dim3(EE/64, BNROWS/128), 256, MMA_SMEM>>>(buv, gamma, beta);

    {   // v: per-batch [N=2048][H=512] -> [H][N]
        float* vin;
        __nv_bfloat16 *th, *tl;
        cudaGetSymbolAddress((void**)&vin, d_v);
        cudaGetSymbolAddress((void**)&th, d_vThi);
        cudaGetSymbolAddress((void**)&tl, d_vTlo);
        transpose_split_kernel<<<dim3(HH/32, NN/32, BB), dim3(32, 8)>>>(vin, th, tl, NN, HH);
    }

    k_qk<<<dim3(NN/64, NN/128, BB), 256, MMA_SMEM>>>();
    k_av<<<dim3(HH/64, NN/128, BB), 256, MMA_SMEM>>>();
    k_o<<<dim3(DD/64, BNROWS/128), 256, MMA_SMEM>>>(bo, out);
}

// round 6
// speedup vs baseline: 1.1396x; 1.1396x over previous
#include <cuda_runtime.h>
#include <cuda_bf16.h>
#include <cstdint>
#include <math.h>

// Problem constants
#define BB 8
#define NN 2048
#define DD 256
#define SS 128
#define HH 512
#define EE 1152          // 2H + S
#define BNROWS (BB*NN)   // 16384
#define RSQRT_S 0.08838834764831845f  // 1/sqrt(128)

// ---- scratch (allocation-free rule: __device__ globals) ----
__device__ __nv_bfloat16 d_xhi[(size_t)BNROWS*DD];
__device__ __nv_bfloat16 d_xlo[(size_t)BNROWS*DD];
__device__ float d_u[(size_t)BNROWS*HH];
__device__ float d_v[(size_t)BNROWS*HH];
__device__ __nv_bfloat16 d_qhi[(size_t)BNROWS*SS];
__device__ __nv_bfloat16 d_qlo[(size_t)BNROWS*SS];
__device__ __nv_bfloat16 d_khi[(size_t)BNROWS*SS];
__device__ __nv_bfloat16 d_klo[(size_t)BNROWS*SS];
__device__ __nv_bfloat16 d_vThi[(size_t)BB*HH*NN];   // [b][h][m]
__device__ __nv_bfloat16 d_vTlo[(size_t)BB*HH*NN];
__device__ __nv_bfloat16 d_ahi[(size_t)BB*NN*NN];    // attn [b][n][m]
__device__ __nv_bfloat16 d_alo[(size_t)BB*NN*NN];
__device__ __nv_bfloat16 d_ghi[(size_t)BNROWS*HH];   // gated hi/lo
__device__ __nv_bfloat16 d_glo[(size_t)BNROWS*HH];
__device__ __nv_bfloat16 d_wuvThi[(size_t)EE*DD];    // W_uv^T [e][d]
__device__ __nv_bfloat16 d_wuvTlo[(size_t)EE*DD];
__device__ __nv_bfloat16 d_woThi[(size_t)DD*HH];     // W_o^T [d][h]
__device__ __nv_bfloat16 d_woTlo[(size_t)DD*HH];

// ============================================================
// Helpers
// ============================================================
__device__ __forceinline__ uint32_t smem_u32(const void* p) {
    uint32_t a;
    asm("{ .reg .u64 t; cvta.to.shared.u64 t, %1; cvt.u32.u64 %0, t; }"
        : "=r"(a) : "l"(p));
    return a;
}

#define LDSM_X4(r0, r1, r2, r3, addr) \
    asm volatile("ldmatrix.sync.aligned.m8n8.x4.shared.b16 {%0,%1,%2,%3}, [%4];" \
        : "=r"(r0), "=r"(r1), "=r"(r2), "=r"(r3) : "r"(addr))

#define MMA16816(d, a, b) \
    asm volatile("mma.sync.aligned.m16n8k16.row.col.f32.bf16.bf16.f32 " \
        "{%0,%1,%2,%3}, {%4,%5,%6,%7}, {%8,%9}, {%0,%1,%2,%3};" \
        : "+f"((d)[0]), "+f"((d)[1]), "+f"((d)[2]), "+f"((d)[3]) \
        : "r"((a)[0]), "r"((a)[1]), "r"((a)[2]), "r"((a)[3]), \
          "r"((b)[0]), "r"((b)[1]))

__device__ __forceinline__ void cp16(uint32_t dst, const __nv_bfloat16* src) {
    asm volatile("cp.async.cg.shared.global [%0], [%1], 16;"
        :: "r"(dst), "l"(src));
}
#define CP_COMMIT() asm volatile("cp.async.commit_group;" ::: "memory")
#define CP_WAIT0()  asm volatile("cp.async.wait_group 0;" ::: "memory")

__device__ __forceinline__ void bf16split(float v, __nv_bfloat16& hi, __nv_bfloat16& lo) {
    hi = __float2bfloat16(v);
    lo = __float2bfloat16(v - __bfloat162float(hi));
}

// ============================================================
// HMMA GEMM core: BM=128, BN=64, BK=64, 256 threads, 2 CTAs/SM.
// A row-major [128][K], B n-major [64][K], hi/lo bf16, 3-term split.
// Warp grid 4x2, warp tile 32x32 (acc[2][4][4]).
// Stage = Ah 16K | Al 16K | Bh 8K | Bl 8K = 48KB, 2 stages (96KB).
// 128B rows, swizzle gi ^= row&7. One __syncthreads per chunk.
// ============================================================
#define STAGE_BYTES 49152
#define MMA_SMEM    (2*STAGE_BYTES)

// ROWS*8 granules of 16B, strided by 256 threads
template <int ROWS>
__device__ __forceinline__ void load_oper(uint32_t dstBase, const __nv_bfloat16* src,
                                          int ld, int kt, int tid) {
    #pragma unroll
    for (int j = 0; j < ROWS*8/256; j++) {
        int g = tid + j * 256;
        int row = g >> 3;
        int gi  = g & 7;
        int gis = gi ^ (row & 7);
        cp16(dstBase + row * 128 + gis * 16, src + (size_t)row * ld + kt + gi * 8);
    }
}

__device__ __forceinline__ void load_chunk(uint32_t sb, int stage,
        const __nv_bfloat16* Ah, const __nv_bfloat16* Al, int ldA,
        const __nv_bfloat16* Bh, const __nv_bfloat16* Bl, int ldB,
        int kt, int tid) {
    uint32_t st = sb + stage * STAGE_BYTES;
    load_oper<128>(st,         Ah, ldA, kt, tid);
    load_oper<128>(st + 16384, Al, ldA, kt, tid);
    load_oper<64> (st + 32768, Bh, ldB, kt, tid);
    load_oper<64> (st + 40960, Bl, ldB, kt, tid);
}

__device__ __forceinline__ void compute_chunk(uint32_t st, int lane, int wm, int wn,
                                              float acc[2][4][4]) {
    const uint32_t aH = st, aL = st + 16384, bH = st + 32768, bL = st + 40960;
    #pragma unroll
    for (int ks = 0; ks < 4; ks++) {
        uint32_t Ahf[2][4], Alf[2][4];
        #pragma unroll
        for (int mi = 0; mi < 2; mi++) {
            int row = wm * 32 + mi * 16 + (lane & 15);
            int gi  = ks * 2 + (lane >> 4);
            uint32_t off = row * 128 + ((gi ^ (row & 7)) * 16);
            LDSM_X4(Ahf[mi][0], Ahf[mi][1], Ahf[mi][2], Ahf[mi][3], aH + off);
            LDSM_X4(Alf[mi][0], Alf[mi][1], Alf[mi][2], Alf[mi][3], aL + off);
        }
        uint32_t Bhf[4][2], Blf[4][2];
        #pragma unroll
        for (int np = 0; np < 2; np++) {
            int row = wn * 32 + np * 16 + (lane & 7) + ((lane >> 4) << 3);
            int gi  = ks * 2 + ((lane >> 3) & 1);
            uint32_t off = row * 128 + ((gi ^ (row & 7)) * 16);
            LDSM_X4(Bhf[2*np][0], Bhf[2*np][1], Bhf[2*np+1][0], Bhf[2*np+1][1], bH + off);
            LDSM_X4(Blf[2*np][0], Blf[2*np][1], Blf[2*np+1][0], Blf[2*np+1][1], bL + off);
        }
        #pragma unroll
        for (int mi = 0; mi < 2; mi++)
            #pragma unroll
            for (int ni = 0; ni < 4; ni++) {
                MMA16816(acc[mi][ni], Ahf[mi], Bhf[ni]);
                MMA16816(acc[mi][ni], Ahf[mi], Blf[ni]);
                MMA16816(acc[mi][ni], Alf[mi], Bhf[ni]);
            }
    }
}

template <class Epi>
__device__ __forceinline__ void mma_gemm_core(
        const __nv_bfloat16* Ah, const __nv_bfloat16* Al, int ldA,
        const __nv_bfloat16* Bh, const __nv_bfloat16* Bl, int ldB,
        int K, char* smem, Epi epi) {
    uint32_t sb = smem_u32(smem);
    int tid = threadIdx.x;
    int lane = tid & 31, warp = tid >> 5;
    int wm = warp & 3, wn = warp >> 2;

    float acc[2][4][4] = {};
    const int nc = K / 64;

    load_chunk(sb, 0, Ah, Al, ldA, Bh, Bl, ldB, 0, tid);
    CP_COMMIT();
    for (int c = 0; c < nc; c++) {
        CP_WAIT0();          // stage c resident
        __syncthreads();     // publish stage c; proves compute(c-1) done by all
        if (c + 1 < nc) {
            load_chunk(sb, (c + 1) & 1, Ah, Al, ldA, Bh, Bl, ldB, (c + 1) * 64, tid);
            CP_COMMIT();
        }
        compute_chunk(sb + (c & 1) * STAGE_BYTES, lane, wm, wn, acc);
    }

    #pragma unroll
    for (int mi = 0; mi < 2; mi++)
        #pragma unroll
        for (int ni = 0; ni < 4; ni++) {
            int r = wm * 32 + mi * 16 + (lane >> 2);
            int c = wn * 32 + ni * 8 + (lane & 3) * 2;
            epi(r,     c, acc[mi][ni][0], acc[mi][ni][1]);
            epi(r + 8, c, acc[mi][ni][2], acc[mi][ni][3]);
        }
}

// ============================================================
// prep: x -> normalized hi/lo bf16
// ============================================================
__global__ void prep_x_kernel(const float* __restrict__ x,
                              const float* __restrict__ g) {
    int row  = blockIdx.x * blockDim.y + threadIdx.y;
    int lane = threadIdx.x;
    const float4* xr = reinterpret_cast<const float4*>(x + (size_t)row * DD);
    float4 a = xr[lane];
    float4 b = xr[lane + 32];
    float s = a.x*a.x + a.y*a.y + a.z*a.z + a.w*a.w
            + b.x*b.x + b.y*b.y + b.z*b.z + b.w*b.w;
    #pragma unroll
    for (int off = 16; off; off >>= 1) s += __shfl_xor_sync(0xffffffffu, s, off);
    s = __shfl_sync(0xffffffffu, s, 0);
    float norm = sqrtf(s * (1.0f / DD));
    float scale = g[0] / fmaxf(norm, 1e-5f);

    float va[8] = {a.x, a.y, a.z, a.w, b.x, b.y, b.z, b.w};
    int idx[2] = {lane * 4, 128 + lane * 4};
    #pragma unroll
    for (int h = 0; h < 2; h++)
        #pragma unroll
        for (int j = 0; j < 4; j++) {
            float v = va[h*4 + j] * scale;
            __nv_bfloat16 hi, lo;
            bf16split(v, hi, lo);
            d_xhi[(size_t)row*DD + idx[h] + j] = hi;
            d_xlo[(size_t)row*DD + idx[h] + j] = lo;
        }
}

// ============================================================
// generic transpose + split:  in [R][C] fp32 -> out [C][R] bf16 hi/lo
// ============================================================
__global__ void transpose_split_kernel(const float* __restrict__ in,
                                       __nv_bfloat16* __restrict__ outh,
                                       __nv_bfloat16* __restrict__ outl,
                                       int R, int C) {
    __shared__ float t[32][33];
    size_t boff = (size_t)blockIdx.z * R * C;
    int c0 = blockIdx.x * 32, r0 = blockIdx.y * 32;
    int tx = threadIdx.x, ty = threadIdx.y;
    #pragma unroll
    for (int i = ty; i < 32; i += 8)
        t[i][tx] = in[boff + (size_t)(r0 + i) * C + c0 + tx];
    __syncthreads();
    #pragma unroll
    for (int i = ty; i < 32; i += 8) {
        float val = t[tx][i];   // = in[r0+tx][c0+i]
        __nv_bfloat16 hi, lo;
        bf16split(val, hi, lo);
        size_t idx = boff + (size_t)(c0 + i) * R + r0 + tx;
        outh[idx] = hi;
        outl[idx] = lo;
    }
}

// ============================================================
// Epilogues
// ============================================================
struct EpiUV {
    int rowBase, colBase;
    const float *buv, *gamma, *beta;
    __device__ void operator()(int r, int c, float v0, float v1) const {
        int row = rowBase + r;
        float vv[2] = {v0, v1};
        #pragma unroll
        for (int i = 0; i < 2; i++) {
            int col = colBase + c + i;
            float val = vv[i] + buv[col];
            val = val / (1.0f + __expf(-val));
            if (col < HH) {
                d_u[(size_t)row*HH + col] = val;
            } else if (col < 2*HH) {
                d_v[(size_t)row*HH + (col - HH)] = val;
            } else {
                int s = col - 2*HH;
                float vq = val * gamma[s]      + beta[s];
                float vk = val * gamma[SS + s] + beta[SS + s];
                size_t qi = (size_t)row*SS + s;
                __nv_bfloat16 hi, lo;
                bf16split(vq, hi, lo); d_qhi[qi] = hi; d_qlo[qi] = lo;
                bf16split(vk, hi, lo); d_khi[qi] = hi; d_klo[qi] = lo;
            }
        }
    }
};

struct EpiQK {
    size_t rowOff;   // b*NN + rowBase
    int colBase;
    __device__ void operator()(int r, int c, float v0, float v1) const {
        size_t idx = (rowOff + r) * NN + colBase + c;
        float a0 = fmaxf(v0 * RSQRT_S, 0.0f); a0 *= a0;
        float a1 = fmaxf(v1 * RSQRT_S, 0.0f); a1 *= a1;
        __nv_bfloat16 h0, l0, h1, l1;
        bf16split(a0, h0, l0);
        bf16split(a1, h1, l1);
        *reinterpret_cast<__nv_bfloat162*>(d_ahi + idx) = __nv_bfloat162{h0, h1};
        *reinterpret_cast<__nv_bfloat162*>(d_alo + idx) = __nv_bfloat162{l0, l1};
    }
};

struct EpiAV {
    size_t rowOff;   // b*NN + rowBase
    int colBase;
    __device__ void operator()(int r, int c, float v0, float v1) const {
        size_t rg = rowOff + r;
        size_t idx = rg * HH + colBase + c;
        float2 uu = *reinterpret_cast<const float2*>(d_u + idx);
        float g0 = uu.x * v0, g1 = uu.y * v1;
        __nv_bfloat16 h0, l0, h1, l1;
        bf16split(g0, h0, l0);
        bf16split(g1, h1, l1);
        *reinterpret_cast<__nv_bfloat162*>(d_ghi + idx) = __nv_bfloat162{h0, h1};
        *reinterpret_cast<__nv_bfloat162*>(d_glo + idx) = __nv_bfloat162{l0, l1};
    }
};

struct EpiO {
    int rowBase, colBase;
    const float* bo;
    float* out;
    __device__ void operator()(int r, int c, float v0, float v1) const {
        int row = rowBase + r;
        int col = colBase + c;
        float2 o = {v0 + bo[col], v1 + bo[col + 1]};
        *reinterpret_cast<float2*>(out + (size_t)row*DD + col) = o;
    }
};

// ============================================================
// GEMM kernels (BN=64 grids)
// ============================================================
__global__ void __launch_bounds__(256, 2)
k_uv(const float* __restrict__ buv, const float* __restrict__ gamma,
     const float* __restrict__ beta) {
    extern __shared__ char smem[];
    int rowBase = blockIdx.y * 128, colBase = blockIdx.x * 64;
    EpiUV epi{rowBase, colBase, buv, gamma, beta};
    mma_gemm_core(d_xhi + (size_t)rowBase * DD, d_xlo + (size_t)rowBase * DD, DD,
                  d_wuvThi + (size_t)colBase * DD, d_wuvTlo + (size_t)colBase * DD, DD,
                  DD, smem, epi);
}

__global__ void __launch_bounds__(256, 2)
k_qk() {
    extern __shared__ char smem[];
    int b = blockIdx.z, rowBase = blockIdx.y * 128, colBase = blockIdx.x * 64;
    size_t ra = (size_t)b * NN + rowBase;
    size_t rb = (size_t)b * NN + colBase;
    EpiQK epi{ra, colBase};
    mma_gemm_core(d_qhi + ra * SS, d_qlo + ra * SS, SS,
                  d_khi + rb * SS, d_klo + rb * SS, SS,
                  SS, smem, epi);
}

__global__ void __launch_bounds__(256, 2)
k_av() {
    extern __shared__ char smem[];
    int b = blockIdx.z, rowBase = blockIdx.y * 128, colBase = blockIdx.x * 64;
    size_t ra = (size_t)b * NN + rowBase;
    size_t hb = (size_t)b * HH + colBase;
    EpiAV epi{ra, colBase};
    mma_gemm_core(d_ahi + ra * NN, d_alo + ra * NN, NN,
                  d_vThi + hb * NN, d_vTlo + hb * NN, NN,
                  NN, smem, epi);
}

__global__ void __launch_bounds__(256, 2)
k_o(const float* __restrict__ bo, float* __restrict__ out) {
    extern __shared__ char smem[];
    int rowBase = blockIdx.y * 128, colBase = blockIdx.x * 64;
    EpiO epi{rowBase, colBase, bo, out};
    mma_gemm_core(d_ghi + (size_t)rowBase * HH, d_glo + (size_t)rowBase * HH, HH,
                  d_woThi + (size_t)colBase * HH, d_woTlo + (size_t)colBase * HH, HH,
                  HH, smem, epi);
}

// ============================================================
extern "C" void kernel_launch(void* const* d_in, const int* in_sizes, int n_in,
                              void* d_out, int out_size) {
    (void)in_sizes; (void)n_in; (void)out_size;
    const float* x     = (const float*)d_in[0];
    const float* g     = (const float*)d_in[1];
    const float* Wuv   = (const float*)d_in[2];
    const float* buv   = (const float*)d_in[3];
    const float* gamma = (const float*)d_in[4];
    const float* beta  = (const float*)d_in[5];
    const float* Wo    = (const float*)d_in[6];
    const float* bo    = (const float*)d_in[7];
    float* out = (float*)d_out;

    static int smem_set = 0;
    if (!smem_set) {
        cudaFuncSetAttribute(k_uv, cudaFuncAttributeMaxDynamicSharedMemorySize, MMA_SMEM);
        cudaFuncSetAttribute(k_qk, cudaFuncAttributeMaxDynamicSharedMemorySize, MMA_SMEM);
        cudaFuncSetAttribute(k_av, cudaFuncAttributeMaxDynamicSharedMemorySize, MMA_SMEM);
        cudaFuncSetAttribute(k_o,  cudaFuncAttributeMaxDynamicSharedMemorySize, MMA_SMEM);
        smem_set = 1;
    }

    prep_x_kernel<<<BNROWS/8, dim3(32, 8)>>>(x, g);

    {   // W_uv: [D=256][E=1152] -> [E][D]
        __nv_bfloat16 *th, *tl;
        cudaGetSymbolAddress((void**)&th, d_wuvThi);
        cudaGetSymbolAddress((void**)&tl, d_wuvTlo);
        transpose_split_kernel<<<dim3(EE/32, DD/32, 1), dim3(32, 8)>>>(Wuv, th, tl, DD, EE);
    }
    {   // W_o: [H=512][D=256] -> [D][H]
        __nv_bfloat16 *th, *tl;
        cudaGetSymbolAddress((void**)&th, d_woThi);
        cudaGetSymbolAddress((void**)&tl, d_woTlo);
        transpose_split_kernel<<<dim3(DD/32, HH/32, 1), dim3(32, 8)>>>(Wo, th, tl, HH, DD);
    }

    k_uv<<<dim3(EE/64, BNROWS/128), 256, MMA_SMEM>>>(buv, gamma, beta);

    {   // v: per-batch [N=2048][H=512] -> [H][N]
        float* vin;
        __nv_bfloat16 *th, *tl;
        cudaGetSymbolAddress((void**)&vin, d_v);
        cudaGetSymbolAddress((void**)&th, d_vThi);
        cudaGetSymbolAddress((void**)&tl, d_vTlo);
        transpose_split_kernel<<<dim3(HH/32, NN/32, BB), dim3(32, 8)>>>(vin, th, tl, NN, HH);
    }

    k_qk<<<dim3(NN/64, NN/128, BB), 256, MMA_SMEM>>>();
    k_av<<<dim3(HH/64, NN/128, BB), 256, MMA_SMEM>>>();
    k_o<<<dim3(DD/64, BNROWS/128), 256, MMA_SMEM>>>(bo, out);
}

// round 7
// speedup vs baseline: 1.2873x; 1.1297x over previous
#include <cuda_runtime.h>
#include <cuda_bf16.h>
#include <cuda_fp16.h>
#include <cstdint>
#include <math.h>

// Problem constants
#define BB 8
#define NN 2048
#define DD 256
#define SS 128
#define HH 512
#define EE 1152          // 2H + S
#define BNROWS (BB*NN)   // 16384
#define RSQRT_S 0.08838834764831845f  // 1/sqrt(128)

// ---- scratch (allocation-free rule: __device__ globals) ----
__device__ __nv_bfloat16 d_xhi[(size_t)BNROWS*DD];
__device__ __nv_bfloat16 d_xlo[(size_t)BNROWS*DD];
__device__ float d_u[(size_t)BNROWS*HH];
__device__ float d_v[(size_t)BNROWS*HH];
__device__ __nv_bfloat16 d_qhi[(size_t)BNROWS*SS];
__device__ __nv_bfloat16 d_qlo[(size_t)BNROWS*SS];
__device__ __nv_bfloat16 d_khi[(size_t)BNROWS*SS];
__device__ __nv_bfloat16 d_klo[(size_t)BNROWS*SS];
__device__ __half d_vT[(size_t)BB*HH*NN];            // [b][h][m] fp16 (truncated)
__device__ __half d_ahi[(size_t)BB*NN*NN];           // attn hi [b][n][m] fp16
__device__ __half d_alo[(size_t)BB*NN*NN];           // attn lo
__device__ __half d_ghi[(size_t)BNROWS*HH];          // gated hi fp16
__device__ __half d_glo[(size_t)BNROWS*HH];          // gated lo
__device__ __nv_bfloat16 d_wuvThi[(size_t)EE*DD];    // W_uv^T [e][d] bf16 hi/lo
__device__ __nv_bfloat16 d_wuvTlo[(size_t)EE*DD];
__device__ __half d_woT[(size_t)DD*HH];              // W_o^T [d][h] fp16 (truncated)

// ============================================================
// Helpers
// ============================================================
__device__ __forceinline__ uint32_t smem_u32(const void* p) {
    uint32_t a;
    asm("{ .reg .u64 t; cvta.to.shared.u64 t, %1; cvt.u32.u64 %0, t; }"
        : "=r"(a) : "l"(p));
    return a;
}

#define LDSM_X4(r0, r1, r2, r3, addr) \
    asm volatile("ldmatrix.sync.aligned.m8n8.x4.shared.b16 {%0,%1,%2,%3}, [%4];" \
        : "=r"(r0), "=r"(r1), "=r"(r2), "=r"(r3) : "r"(addr))

#define MMA_BF16(d, a, b) \
    asm volatile("mma.sync.aligned.m16n8k16.row.col.f32.bf16.bf16.f32 " \
        "{%0,%1,%2,%3}, {%4,%5,%6,%7}, {%8,%9}, {%0,%1,%2,%3};" \
        : "+f"((d)[0]), "+f"((d)[1]), "+f"((d)[2]), "+f"((d)[3]) \
        : "r"((a)[0]), "r"((a)[1]), "r"((a)[2]), "r"((a)[3]), \
          "r"((b)[0]), "r"((b)[1]))

#define MMA_F16(d, a, b) \
    asm volatile("mma.sync.aligned.m16n8k16.row.col.f32.f16.f16.f32 " \
        "{%0,%1,%2,%3}, {%4,%5,%6,%7}, {%8,%9}, {%0,%1,%2,%3};" \
        : "+f"((d)[0]), "+f"((d)[1]), "+f"((d)[2]), "+f"((d)[3]) \
        : "r"((a)[0]), "r"((a)[1]), "r"((a)[2]), "r"((a)[3]), \
          "r"((b)[0]), "r"((b)[1]))

__device__ __forceinline__ void cp16(uint32_t dst, const void* src) {
    asm volatile("cp.async.cg.shared.global [%0], [%1], 16;"
        :: "r"(dst), "l"(src));
}
#define CP_COMMIT() asm volatile("cp.async.commit_group;" ::: "memory")
#define CP_WAIT0()  asm volatile("cp.async.wait_group 0;" ::: "memory")

__device__ __forceinline__ void bf16split(float v, __nv_bfloat16& hi, __nv_bfloat16& lo) {
    hi = __float2bfloat16(v);
    lo = __float2bfloat16(v - __bfloat162float(hi));
}
__device__ __forceinline__ void f16split(float v, __half& hi, __half& lo) {
    hi = __float2half_rn(v);
    lo = __float2half_rn(v - __half2float(hi));
}

// 16B granule loader: ROWS*8 granules strided by 256 threads, 128B rows,
// swizzle gi ^= row&7.
template <int ROWS, class T>
__device__ __forceinline__ void load_oper(uint32_t dstBase, const T* src,
                                          int ld, int kt, int tid) {
    #pragma unroll
    for (int j = 0; j < ROWS*8/256; j++) {
        int g = tid + j * 256;
        int row = g >> 3;
        int gi  = g & 7;
        int gis = gi ^ (row & 7);
        cp16(dstBase + row * 128 + gis * 16, src + (size_t)row * ld + kt + gi * 8);
    }
}

// ============================================================
// bf16 3-term core (R6, proven): BM=128, BN=64, BK=64, 2 CTAs/SM.
// Stage = Ah 16K | Al 16K | Bh 8K | Bl 8K = 48KB, 2 stages.
// ============================================================
#define STAGE_B  49152
#define SMEM_B3  (2*STAGE_B)

__device__ __forceinline__ void load_chunk_b(uint32_t sb, int stage,
        const __nv_bfloat16* Ah, const __nv_bfloat16* Al, int ldA,
        const __nv_bfloat16* Bh, const __nv_bfloat16* Bl, int ldB,
        int kt, int tid) {
    uint32_t st = sb + stage * STAGE_B;
    load_oper<128>(st,         Ah, ldA, kt, tid);
    load_oper<128>(st + 16384, Al, ldA, kt, tid);
    load_oper<64> (st + 32768, Bh, ldB, kt, tid);
    load_oper<64> (st + 40960, Bl, ldB, kt, tid);
}

__device__ __forceinline__ void compute_chunk_b(uint32_t st, int lane, int wm, int wn,
                                                float acc[2][4][4]) {
    const uint32_t aH = st, aL = st + 16384, bH = st + 32768, bL = st + 40960;
    #pragma unroll
    for (int ks = 0; ks < 4; ks++) {
        uint32_t Ahf[2][4], Alf[2][4];
        #pragma unroll
        for (int mi = 0; mi < 2; mi++) {
            int row = wm * 32 + mi * 16 + (lane & 15);
            int gi  = ks * 2 + (lane >> 4);
            uint32_t off = row * 128 + ((gi ^ (row & 7)) * 16);
            LDSM_X4(Ahf[mi][0], Ahf[mi][1], Ahf[mi][2], Ahf[mi][3], aH + off);
            LDSM_X4(Alf[mi][0], Alf[mi][1], Alf[mi][2], Alf[mi][3], aL + off);
        }
        uint32_t Bhf[4][2], Blf[4][2];
        #pragma unroll
        for (int np = 0; np < 2; np++) {
            int row = wn * 32 + np * 16 + (lane & 7) + ((lane >> 4) << 3);
            int gi  = ks * 2 + ((lane >> 3) & 1);
            uint32_t off = row * 128 + ((gi ^ (row & 7)) * 16);
            LDSM_X4(Bhf[2*np][0], Bhf[2*np][1], Bhf[2*np+1][0], Bhf[2*np+1][1], bH + off);
            LDSM_X4(Blf[2*np][0], Blf[2*np][1], Blf[2*np+1][0], Blf[2*np+1][1], bL + off);
        }
        #pragma unroll
        for (int mi = 0; mi < 2; mi++)
            #pragma unroll
            for (int ni = 0; ni < 4; ni++) {
                MMA_BF16(acc[mi][ni], Ahf[mi], Bhf[ni]);
                MMA_BF16(acc[mi][ni], Ahf[mi], Blf[ni]);
                MMA_BF16(acc[mi][ni], Alf[mi], Bhf[ni]);
            }
    }
}

template <class Epi>
__device__ __forceinline__ void core_bf16(
        const __nv_bfloat16* Ah, const __nv_bfloat16* Al, int ldA,
        const __nv_bfloat16* Bh, const __nv_bfloat16* Bl, int ldB,
        int K, char* smem, Epi epi) {
    uint32_t sb = smem_u32(smem);
    int tid = threadIdx.x;
    int lane = tid & 31, warp = tid >> 5;
    int wm = warp & 3, wn = warp >> 2;

    float acc[2][4][4] = {};
    const int nc = K / 64;

    load_chunk_b(sb, 0, Ah, Al, ldA, Bh, Bl, ldB, 0, tid);
    CP_COMMIT();
    for (int c = 0; c < nc; c++) {
        CP_WAIT0();
        __syncthreads();
        if (c + 1 < nc) {
            load_chunk_b(sb, (c + 1) & 1, Ah, Al, ldA, Bh, Bl, ldB, (c + 1) * 64, tid);
            CP_COMMIT();
        }
        compute_chunk_b(sb + (c & 1) * STAGE_B, lane, wm, wn, acc);
    }

    #pragma unroll
    for (int mi = 0; mi < 2; mi++)
        #pragma unroll
        for (int ni = 0; ni < 4; ni++) {
            int r = wm * 32 + mi * 16 + (lane >> 2);
            int c = wn * 32 + ni * 8 + (lane & 3) * 2;
            epi(r,     c, acc[mi][ni][0], acc[mi][ni][1]);
            epi(r + 8, c, acc[mi][ni][2], acc[mi][ni][3]);
        }
}

// ============================================================
// fp16 2-term core: BM=128, BN=128, BK=64, 2 CTAs/SM.
// A fp16 hi/lo (split exact), B fp16 (truncated).
// Stage = Ah 16K | Al 16K | Bh 16K = 48KB, 2 stages.
// Warp grid 4x2, warp tile 32x64 (acc[2][8][4]).
// ============================================================
__device__ __forceinline__ void load_chunk_h(uint32_t sb, int stage,
        const __half* Ah, const __half* Al, int ldA,
        const __half* Bh, int ldB, int kt, int tid) {
    uint32_t st = sb + stage * STAGE_B;
    load_oper<128>(st,         Ah, ldA, kt, tid);
    load_oper<128>(st + 16384, Al, ldA, kt, tid);
    load_oper<128>(st + 32768, Bh, ldB, kt, tid);
}

__device__ __forceinline__ void compute_chunk_h(uint32_t st, int lane, int wm, int wn,
                                                float acc[2][8][4]) {
    const uint32_t aH = st, aL = st + 16384, bH = st + 32768;
    #pragma unroll
    for (int ks = 0; ks < 4; ks++) {
        uint32_t Ahf[2][4], Alf[2][4];
        #pragma unroll
        for (int mi = 0; mi < 2; mi++) {
            int row = wm * 32 + mi * 16 + (lane & 15);
            int gi  = ks * 2 + (lane >> 4);
            uint32_t off = row * 128 + ((gi ^ (row & 7)) * 16);
            LDSM_X4(Ahf[mi][0], Ahf[mi][1], Ahf[mi][2], Ahf[mi][3], aH + off);
            LDSM_X4(Alf[mi][0], Alf[mi][1], Alf[mi][2], Alf[mi][3], aL + off);
        }
        uint32_t Bhf[8][2];
        #pragma unroll
        for (int np = 0; np < 4; np++) {
            int row = wn * 64 + np * 16 + (lane & 7) + ((lane >> 4) << 3);
            int gi  = ks * 2 + ((lane >> 3) & 1);
            uint32_t off = row * 128 + ((gi ^ (row & 7)) * 16);
            LDSM_X4(Bhf[2*np][0], Bhf[2*np][1], Bhf[2*np+1][0], Bhf[2*np+1][1], bH + off);
        }
        #pragma unroll
        for (int mi = 0; mi < 2; mi++)
            #pragma unroll
            for (int ni = 0; ni < 8; ni++) {
                MMA_F16(acc[mi][ni], Ahf[mi], Bhf[ni]);
                MMA_F16(acc[mi][ni], Alf[mi], Bhf[ni]);
            }
    }
}

template <class Epi>
__device__ __forceinline__ void core_f16(
        const __half* Ah, const __half* Al, int ldA,
        const __half* Bh, int ldB, int K, char* smem, Epi epi) {
    uint32_t sb = smem_u32(smem);
    int tid = threadIdx.x;
    int lane = tid & 31, warp = tid >> 5;
    int wm = warp & 3, wn = warp >> 2;

    float acc[2][8][4] = {};
    const int nc = K / 64;

    load_chunk_h(sb, 0, Ah, Al, ldA, Bh, ldB, 0, tid);
    CP_COMMIT();
    for (int c = 0; c < nc; c++) {
        CP_WAIT0();
        __syncthreads();
        if (c + 1 < nc) {
            load_chunk_h(sb, (c + 1) & 1, Ah, Al, ldA, Bh, ldB, (c + 1) * 64, tid);
            CP_COMMIT();
        }
        compute_chunk_h(sb + (c & 1) * STAGE_B, lane, wm, wn, acc);
    }

    #pragma unroll
    for (int mi = 0; mi < 2; mi++)
        #pragma unroll
        for (int ni = 0; ni < 8; ni++) {
            int r = wm * 32 + mi * 16 + (lane >> 2);
            int c = wn * 64 + ni * 8 + (lane & 3) * 2;
            epi(r,     c, acc[mi][ni][0], acc[mi][ni][1]);
            epi(r + 8, c, acc[mi][ni][2], acc[mi][ni][3]);
        }
}

// ============================================================
// prep: x -> normalized hi/lo bf16
// ============================================================
__global__ void prep_x_kernel(const float* __restrict__ x,
                              const float* __restrict__ g) {
    int row  = blockIdx.x * blockDim.y + threadIdx.y;
    int lane = threadIdx.x;
    const float4* xr = reinterpret_cast<const float4*>(x + (size_t)row * DD);
    float4 a = xr[lane];
    float4 b = xr[lane + 32];
    float s = a.x*a.x + a.y*a.y + a.z*a.z + a.w*a.w
            + b.x*b.x + b.y*b.y + b.z*b.z + b.w*b.w;
    #pragma unroll
    for (int off = 16; off; off >>= 1) s += __shfl_xor_sync(0xffffffffu, s, off);
    s = __shfl_sync(0xffffffffu, s, 0);
    float norm = sqrtf(s * (1.0f / DD));
    float scale = g[0] / fmaxf(norm, 1e-5f);

    float va[8] = {a.x, a.y, a.z, a.w, b.x, b.y, b.z, b.w};
    int idx[2] = {lane * 4, 128 + lane * 4};
    #pragma unroll
    for (int h = 0; h < 2; h++)
        #pragma unroll
        for (int j = 0; j < 4; j++) {
            float v = va[h*4 + j] * scale;
            __nv_bfloat16 hi, lo;
            bf16split(v, hi, lo);
            d_xhi[(size_t)row*DD + idx[h] + j] = hi;
            d_xlo[(size_t)row*DD + idx[h] + j] = lo;
        }
}

// ============================================================
// transpose + bf16 split (for W_uv)
// ============================================================
__global__ void transpose_split_kernel(const float* __restrict__ in,
                                       __nv_bfloat16* __restrict__ outh,
                                       __nv_bfloat16* __restrict__ outl,
                                       int R, int C) {
    __shared__ float t[32][33];
    size_t boff = (size_t)blockIdx.z * R * C;
    int c0 = blockIdx.x * 32, r0 = blockIdx.y * 32;
    int tx = threadIdx.x, ty = threadIdx.y;
    #pragma unroll
    for (int i = ty; i < 32; i += 8)
        t[i][tx] = in[boff + (size_t)(r0 + i) * C + c0 + tx];
    __syncthreads();
    #pragma unroll
    for (int i = ty; i < 32; i += 8) {
        float val = t[tx][i];
        __nv_bfloat16 hi, lo;
        bf16split(val, hi, lo);
        size_t idx = boff + (size_t)(c0 + i) * R + r0 + tx;
        outh[idx] = hi;
        outl[idx] = lo;
    }
}

// transpose + fp16 truncate (for v, W_o)
__global__ void transpose_half_kernel(const float* __restrict__ in,
                                      __half* __restrict__ outh,
                                      int R, int C) {
    __shared__ float t[32][33];
    size_t boff = (size_t)blockIdx.z * R * C;
    int c0 = blockIdx.x * 32, r0 = blockIdx.y * 32;
    int tx = threadIdx.x, ty = threadIdx.y;
    #pragma unroll
    for (int i = ty; i < 32; i += 8)
        t[i][tx] = in[boff + (size_t)(r0 + i) * C + c0 + tx];
    __syncthreads();
    #pragma unroll
    for (int i = ty; i < 32; i += 8) {
        size_t idx = boff + (size_t)(c0 + i) * R + r0 + tx;
        outh[idx] = __float2half_rn(t[tx][i]);
    }
}

// ============================================================
// Epilogues
// ============================================================
struct EpiUV {
    int rowBase, colBase;
    const float *buv, *gamma, *beta;
    __device__ void operator()(int r, int c, float v0, float v1) const {
        int row = rowBase + r;
        float vv[2] = {v0, v1};
        #pragma unroll
        for (int i = 0; i < 2; i++) {
            int col = colBase + c + i;
            float val = vv[i] + buv[col];
            val = val / (1.0f + __expf(-val));
            if (col < HH) {
                d_u[(size_t)row*HH + col] = val;
            } else if (col < 2*HH) {
                d_v[(size_t)row*HH + (col - HH)] = val;
            } else {
                int s = col - 2*HH;
                float vq = val * gamma[s]      + beta[s];
                float vk = val * gamma[SS + s] + beta[SS + s];
                size_t qi = (size_t)row*SS + s;
                __nv_bfloat16 hi, lo;
                bf16split(vq, hi, lo); d_qhi[qi] = hi; d_qlo[qi] = lo;
                bf16split(vk, hi, lo); d_khi[qi] = hi; d_klo[qi] = lo;
            }
        }
    }
};

struct EpiQK {
    size_t rowOff;   // b*NN + rowBase
    int colBase;
    __device__ void operator()(int r, int c, float v0, float v1) const {
        size_t idx = (rowOff + r) * NN + colBase + c;
        float a0 = fmaxf(v0 * RSQRT_S, 0.0f); a0 *= a0;
        float a1 = fmaxf(v1 * RSQRT_S, 0.0f); a1 *= a1;
        __half h0, l0, h1, l1;
        f16split(a0, h0, l0);
        f16split(a1, h1, l1);
        *reinterpret_cast<__half2*>(d_ahi + idx) = __halves2half2(h0, h1);
        *reinterpret_cast<__half2*>(d_alo + idx) = __halves2half2(l0, l1);
    }
};

struct EpiAV {
    size_t rowOff;   // b*NN + rowBase
    int colBase;
    __device__ void operator()(int r, int c, float v0, float v1) const {
        size_t rg = rowOff + r;
        size_t idx = rg * HH + colBase + c;
        float2 uu = *reinterpret_cast<const float2*>(d_u + idx);
        float g0 = uu.x * v0, g1 = uu.y * v1;
        __half h0, l0, h1, l1;
        f16split(g0, h0, l0);
        f16split(g1, h1, l1);
        *reinterpret_cast<__half2*>(d_ghi + idx) = __halves2half2(h0, h1);
        *reinterpret_cast<__half2*>(d_glo + idx) = __halves2half2(l0, l1);
    }
};

struct EpiO {
    int rowBase, colBase;
    const float* bo;
    float* out;
    __device__ void operator()(int r, int c, float v0, float v1) const {
        int row = rowBase + r;
        int col = colBase + c;
        float2 o = {v0 + bo[col], v1 + bo[col + 1]};
        *reinterpret_cast<float2*>(out + (size_t)row*DD + col) = o;
    }
};

// ============================================================
// GEMM kernels
// ============================================================
__global__ void __launch_bounds__(256, 2)
k_uv(const float* __restrict__ buv, const float* __restrict__ gamma,
     const float* __restrict__ beta) {
    extern __shared__ char smem[];
    int rowBase = blockIdx.y * 128, colBase = blockIdx.x * 64;
    EpiUV epi{rowBase, colBase, buv, gamma, beta};
    core_bf16(d_xhi + (size_t)rowBase * DD, d_xlo + (size_t)rowBase * DD, DD,
              d_wuvThi + (size_t)colBase * DD, d_wuvTlo + (size_t)colBase * DD, DD,
              DD, smem, epi);
}

__global__ void __launch_bounds__(256, 2)
k_qk() {
    extern __shared__ char smem[];
    int b = blockIdx.z, rowBase = blockIdx.y * 128, colBase = blockIdx.x * 64;
    size_t ra = (size_t)b * NN + rowBase;
    size_t rb = (size_t)b * NN + colBase;
    EpiQK epi{ra, colBase};
    core_bf16(d_qhi + ra * SS, d_qlo + ra * SS, SS,
              d_khi + rb * SS, d_klo + rb * SS, SS,
              SS, smem, epi);
}

__global__ void __launch_bounds__(256, 2)
k_av() {
    extern __shared__ char smem[];
    int b = blockIdx.z, rowBase = blockIdx.y * 128, colBase = blockIdx.x * 128;
    size_t ra = (size_t)b * NN + rowBase;
    size_t hb = (size_t)b * HH + colBase;
    EpiAV epi{ra, colBase};
    core_f16(d_ahi + ra * NN, d_alo + ra * NN, NN,
             d_vT + hb * NN, NN,
             NN, smem, epi);
}

__global__ void __launch_bounds__(256, 2)
k_o(const float* __restrict__ bo, float* __restrict__ out) {
    extern __shared__ char smem[];
    int rowBase = blockIdx.y * 128, colBase = blockIdx.x * 128;
    EpiO epi{rowBase, colBase, bo, out};
    core_f16(d_ghi + (size_t)rowBase * HH, d_glo + (size_t)rowBase * HH, HH,
             d_woT + (size_t)colBase * HH, HH,
             HH, smem, epi);
}

// ============================================================
extern "C" void kernel_launch(void* const* d_in, const int* in_sizes, int n_in,
                              void* d_out, int out_size) {
    (void)in_sizes; (void)n_in; (void)out_size;
    const float* x     = (const float*)d_in[0];
    const float* g     = (const float*)d_in[1];
    const float* Wuv   = (const float*)d_in[2];
    const float* buv   = (const float*)d_in[3];
    const float* gamma = (const float*)d_in[4];
    const float* beta  = (const float*)d_in[5];
    const float* Wo    = (const float*)d_in[6];
    const float* bo    = (const float*)d_in[7];
    float* out = (float*)d_out;

    static int smem_set = 0;
    if (!smem_set) {
        cudaFuncSetAttribute(k_uv, cudaFuncAttributeMaxDynamicSharedMemorySize, SMEM_B3);
        cudaFuncSetAttribute(k_qk, cudaFuncAttributeMaxDynamicSharedMemorySize, SMEM_B3);
        cudaFuncSetAttribute(k_av, cudaFuncAttributeMaxDynamicSharedMemorySize, SMEM_B3);
        cudaFuncSetAttribute(k_o,  cudaFuncAttributeMaxDynamicSharedMemorySize, SMEM_B3);
        smem_set = 1;
    }

    prep_x_kernel<<<BNROWS/8, dim3(32, 8)>>>(x, g);

    {   // W_uv: [D=256][E=1152] -> [E][D] bf16 hi/lo
        __nv_bfloat16 *th, *tl;
        cudaGetSymbolAddress((void**)&th, d_wuvThi);
        cudaGetSymbolAddress((void**)&tl, d_wuvTlo);
        transpose_split_kernel<<<dim3(EE/32, DD/32, 1), dim3(32, 8)>>>(Wuv, th, tl, DD, EE);
    }
    {   // W_o: [H=512][D=256] -> [D][H] fp16
        __half* th;
        cudaGetSymbolAddress((void**)&th, d_woT);
        transpose_half_kernel<<<dim3(DD/32, HH/32, 1), dim3(32, 8)>>>(Wo, th, HH, DD);
    }

    k_uv<<<dim3(EE/64, BNROWS/128), 256, SMEM_B3>>>(buv, gamma, beta);

    {   // v: per-batch [N=2048][H=512] -> [H][N] fp16
        float* vin;
        __half* th;
        cudaGetSymbolAddress((void**)&vin, d_v);
        cudaGetSymbolAddress((void**)&th, d_vT);
        transpose_half_kernel<<<dim3(HH/32, NN/32, BB), dim3(32, 8)>>>(vin, th, NN, HH);
    }

    k_qk<<<dim3(NN/64, NN/128, BB), 256, SMEM_B3>>>();
    k_av<<<dim3(HH/128, NN/128, BB), 256, SMEM_B3>>>();
    k_o<<<dim3(DD/128, BNROWS/128), 256, SMEM_B3>>>(bo, out);
}

// round 8
// speedup vs baseline: 1.3370x; 1.0386x over previous
#include <cuda_runtime.h>
#include <cuda_bf16.h>
#include <cuda_fp16.h>
#include <cstdint>
#include <math.h>

// Problem constants
#define BB 8
#define NN 2048
#define DD 256
#define SS 128
#define HH 512
#define EE 1152          // 2H + S
#define BNROWS (BB*NN)   // 16384
#define RSQRT_S 0.08838834764831845f  // 1/sqrt(128)

// ---- scratch (allocation-free rule: __device__ globals) ----
__device__ __nv_bfloat16 d_xhi[(size_t)BNROWS*DD];
__device__ __nv_bfloat16 d_xlo[(size_t)BNROWS*DD];
__device__ __half d_xh16[(size_t)BNROWS*DD];         // xn fp16 hi/lo (exact split)
__device__ __half d_xl16[(size_t)BNROWS*DD];
__device__ float d_u[(size_t)BNROWS*HH];
__device__ float d_v[(size_t)BNROWS*HH];
__device__ __nv_bfloat16 d_qhi[(size_t)BNROWS*SS];
__device__ __nv_bfloat16 d_qlo[(size_t)BNROWS*SS];
__device__ __nv_bfloat16 d_khi[(size_t)BNROWS*SS];
__device__ __nv_bfloat16 d_klo[(size_t)BNROWS*SS];
__device__ __half d_vT[(size_t)BB*HH*NN];            // [b][h][m] fp16 (truncated)
__device__ __half d_ahi[(size_t)BB*NN*NN];           // attn hi [b][n][m] fp16
__device__ __half d_alo[(size_t)BB*NN*NN];           // attn lo
__device__ __half d_ghi[(size_t)BNROWS*HH];          // gated hi fp16
__device__ __half d_glo[(size_t)BNROWS*HH];          // gated lo
__device__ __nv_bfloat16 d_wuvThi[(size_t)EE*DD];    // W_uv^T [e][d] bf16 hi/lo
__device__ __nv_bfloat16 d_wuvTlo[(size_t)EE*DD];
__device__ __half d_wuvTh16[(size_t)EE*DD];          // W_uv^T fp16 (truncated)
__device__ __half d_woT[(size_t)DD*HH];              // W_o^T [d][h] fp16 (truncated)

// ============================================================
// Helpers
// ============================================================
__device__ __forceinline__ uint32_t smem_u32(const void* p) {
    uint32_t a;
    asm("{ .reg .u64 t; cvta.to.shared.u64 t, %1; cvt.u32.u64 %0, t; }"
        : "=r"(a) : "l"(p));
    return a;
}

#define LDSM_X4(r0, r1, r2, r3, addr) \
    asm volatile("ldmatrix.sync.aligned.m8n8.x4.shared.b16 {%0,%1,%2,%3}, [%4];" \
        : "=r"(r0), "=r"(r1), "=r"(r2), "=r"(r3) : "r"(addr))

#define MMA_BF16(d, a, b) \
    asm volatile("mma.sync.aligned.m16n8k16.row.col.f32.bf16.bf16.f32 " \
        "{%0,%1,%2,%3}, {%4,%5,%6,%7}, {%8,%9}, {%0,%1,%2,%3};" \
        : "+f"((d)[0]), "+f"((d)[1]), "+f"((d)[2]), "+f"((d)[3]) \
        : "r"((a)[0]), "r"((a)[1]), "r"((a)[2]), "r"((a)[3]), \
          "r"((b)[0]), "r"((b)[1]))

#define MMA_F16(d, a, b) \
    asm volatile("mma.sync.aligned.m16n8k16.row.col.f32.f16.f16.f32 " \
        "{%0,%1,%2,%3}, {%4,%5,%6,%7}, {%8,%9}, {%0,%1,%2,%3};" \
        : "+f"((d)[0]), "+f"((d)[1]), "+f"((d)[2]), "+f"((d)[3]) \
        : "r"((a)[0]), "r"((a)[1]), "r"((a)[2]), "r"((a)[3]), \
          "r"((b)[0]), "r"((b)[1]))

__device__ __forceinline__ void cp16(uint32_t dst, const void* src) {
    asm volatile("cp.async.cg.shared.global [%0], [%1], 16;"
        :: "r"(dst), "l"(src));
}
#define CP_COMMIT() asm volatile("cp.async.commit_group;" ::: "memory")
#define CP_WAIT0()  asm volatile("cp.async.wait_group 0;" ::: "memory")

__device__ __forceinline__ void bf16split(float v, __nv_bfloat16& hi, __nv_bfloat16& lo) {
    hi = __float2bfloat16(v);
    lo = __float2bfloat16(v - __bfloat162float(hi));
}
__device__ __forceinline__ void f16split(float v, __half& hi, __half& lo) {
    hi = __float2half_rn(v);
    lo = __float2half_rn(v - __half2float(hi));
}

// 16B granule loader: ROWS*8 granules strided by 256 threads, 128B rows,
// swizzle gi ^= row&7.
template <int ROWS, class T>
__device__ __forceinline__ void load_oper(uint32_t dstBase, const T* src,
                                          int ld, int kt, int tid) {
    #pragma unroll
    for (int j = 0; j < ROWS*8/256; j++) {
        int g = tid + j * 256;
        int row = g >> 3;
        int gi  = g & 7;
        int gis = gi ^ (row & 7);
        cp16(dstBase + row * 128 + gis * 16, src + (size_t)row * ld + kt + gi * 8);
    }
}

// ============================================================
// bf16 3-term core: BM=128, BN=64, BK=64, 2 CTAs/SM.
// ============================================================
#define STAGE_B  49152
#define SMEM_B3  (2*STAGE_B)

__device__ __forceinline__ void load_chunk_b(uint32_t sb, int stage,
        const __nv_bfloat16* Ah, const __nv_bfloat16* Al, int ldA,
        const __nv_bfloat16* Bh, const __nv_bfloat16* Bl, int ldB,
        int kt, int tid) {
    uint32_t st = sb + stage * STAGE_B;
    load_oper<128>(st,         Ah, ldA, kt, tid);
    load_oper<128>(st + 16384, Al, ldA, kt, tid);
    load_oper<64> (st + 32768, Bh, ldB, kt, tid);
    load_oper<64> (st + 40960, Bl, ldB, kt, tid);
}

__device__ __forceinline__ void compute_chunk_b(uint32_t st, int lane, int wm, int wn,
                                                float acc[2][4][4]) {
    const uint32_t aH = st, aL = st + 16384, bH = st + 32768, bL = st + 40960;
    #pragma unroll
    for (int ks = 0; ks < 4; ks++) {
        uint32_t Ahf[2][4], Alf[2][4];
        #pragma unroll
        for (int mi = 0; mi < 2; mi++) {
            int row = wm * 32 + mi * 16 + (lane & 15);
            int gi  = ks * 2 + (lane >> 4);
            uint32_t off = row * 128 + ((gi ^ (row & 7)) * 16);
            LDSM_X4(Ahf[mi][0], Ahf[mi][1], Ahf[mi][2], Ahf[mi][3], aH + off);
            LDSM_X4(Alf[mi][0], Alf[mi][1], Alf[mi][2], Alf[mi][3], aL + off);
        }
        uint32_t Bhf[4][2], Blf[4][2];
        #pragma unroll
        for (int np = 0; np < 2; np++) {
            int row = wn * 32 + np * 16 + (lane & 7) + ((lane >> 4) << 3);
            int gi  = ks * 2 + ((lane >> 3) & 1);
            uint32_t off = row * 128 + ((gi ^ (row & 7)) * 16);
            LDSM_X4(Bhf[2*np][0], Bhf[2*np][1], Bhf[2*np+1][0], Bhf[2*np+1][1], bH + off);
            LDSM_X4(Blf[2*np][0], Blf[2*np][1], Blf[2*np+1][0], Blf[2*np+1][1], bL + off);
        }
        #pragma unroll
        for (int mi = 0; mi < 2; mi++)
            #pragma unroll
            for (int ni = 0; ni < 4; ni++) {
                MMA_BF16(acc[mi][ni], Ahf[mi], Bhf[ni]);
                MMA_BF16(acc[mi][ni], Ahf[mi], Blf[ni]);
                MMA_BF16(acc[mi][ni], Alf[mi], Bhf[ni]);
            }
    }
}

template <class Epi>
__device__ __forceinline__ void core_bf16(
        const __nv_bfloat16* Ah, const __nv_bfloat16* Al, int ldA,
        const __nv_bfloat16* Bh, const __nv_bfloat16* Bl, int ldB,
        int K, char* smem, Epi epi) {
    uint32_t sb = smem_u32(smem);
    int tid = threadIdx.x;
    int lane = tid & 31, warp = tid >> 5;
    int wm = warp & 3, wn = warp >> 2;

    float acc[2][4][4] = {};
    const int nc = K / 64;

    load_chunk_b(sb, 0, Ah, Al, ldA, Bh, Bl, ldB, 0, tid);
    CP_COMMIT();
    for (int c = 0; c < nc; c++) {
        CP_WAIT0();
        __syncthreads();
        if (c + 1 < nc) {
            load_chunk_b(sb, (c + 1) & 1, Ah, Al, ldA, Bh, Bl, ldB, (c + 1) * 64, tid);
            CP_COMMIT();
        }
        compute_chunk_b(sb + (c & 1) * STAGE_B, lane, wm, wn, acc);
    }

    #pragma unroll
    for (int mi = 0; mi < 2; mi++)
        #pragma unroll
        for (int ni = 0; ni < 4; ni++) {
            int r = wm * 32 + mi * 16 + (lane >> 2);
            int c = wn * 32 + ni * 8 + (lane & 3) * 2;
            epi(r,     c, acc[mi][ni][0], acc[mi][ni][1]);
            epi(r + 8, c, acc[mi][ni][2], acc[mi][ni][3]);
        }
}

// ============================================================
// fp16 2-term core: BM=128, BN=128, BK=64, 2 CTAs/SM.
// A fp16 hi/lo (exact split), B fp16 (truncated).
// ============================================================
__device__ __forceinline__ void load_chunk_h(uint32_t sb, int stage,
        const __half* Ah, const __half* Al, int ldA,
        const __half* Bh, int ldB, int kt, int tid) {
    uint32_t st = sb + stage * STAGE_B;
    load_oper<128>(st,         Ah, ldA, kt, tid);
    load_oper<128>(st + 16384, Al, ldA, kt, tid);
    load_oper<128>(st + 32768, Bh, ldB, kt, tid);
}

__device__ __forceinline__ void compute_chunk_h(uint32_t st, int lane, int wm, int wn,
                                                float acc[2][8][4]) {
    const uint32_t aH = st, aL = st + 16384, bH = st + 32768;
    #pragma unroll
    for (int ks = 0; ks < 4; ks++) {
        uint32_t Ahf[2][4], Alf[2][4];
        #pragma unroll
        for (int mi = 0; mi < 2; mi++) {
            int row = wm * 32 + mi * 16 + (lane & 15);
            int gi  = ks * 2 + (lane >> 4);
            uint32_t off = row * 128 + ((gi ^ (row & 7)) * 16);
            LDSM_X4(Ahf[mi][0], Ahf[mi][1], Ahf[mi][2], Ahf[mi][3], aH + off);
            LDSM_X4(Alf[mi][0], Alf[mi][1], Alf[mi][2], Alf[mi][3], aL + off);
        }
        uint32_t Bhf[8][2];
        #pragma unroll
        for (int np = 0; np < 4; np++) {
            int row = wn * 64 + np * 16 + (lane & 7) + ((lane >> 4) << 3);
            int gi  = ks * 2 + ((lane >> 3) & 1);
            uint32_t off = row * 128 + ((gi ^ (row & 7)) * 16);
            LDSM_X4(Bhf[2*np][0], Bhf[2*np][1], Bhf[2*np+1][0], Bhf[2*np+1][1], bH + off);
        }
        #pragma unroll
        for (int mi = 0; mi < 2; mi++)
            #pragma unroll
            for (int ni = 0; ni < 8; ni++) {
                MMA_F16(acc[mi][ni], Ahf[mi], Bhf[ni]);
                MMA_F16(acc[mi][ni], Alf[mi], Bhf[ni]);
            }
    }
}

template <class Epi>
__device__ __forceinline__ void core_f16(
        const __half* Ah, const __half* Al, int ldA,
        const __half* Bh, int ldB, int K, char* smem, Epi epi) {
    uint32_t sb = smem_u32(smem);
    int tid = threadIdx.x;
    int lane = tid & 31, warp = tid >> 5;
    int wm = warp & 3, wn = warp >> 2;

    float acc[2][8][4] = {};
    const int nc = K / 64;

    load_chunk_h(sb, 0, Ah, Al, ldA, Bh, ldB, 0, tid);
    CP_COMMIT();
    for (int c = 0; c < nc; c++) {
        CP_WAIT0();
        __syncthreads();
        if (c + 1 < nc) {
            load_chunk_h(sb, (c + 1) & 1, Ah, Al, ldA, Bh, ldB, (c + 1) * 64, tid);
            CP_COMMIT();
        }
        compute_chunk_h(sb + (c & 1) * STAGE_B, lane, wm, wn, acc);
    }

    #pragma unroll
    for (int mi = 0; mi < 2; mi++)
        #pragma unroll
        for (int ni = 0; ni < 8; ni++) {
            int r = wm * 32 + mi * 16 + (lane >> 2);
            int c = wn * 64 + ni * 8 + (lane & 3) * 2;
            epi(r,     c, acc[mi][ni][0], acc[mi][ni][1]);
            epi(r + 8, c, acc[mi][ni][2], acc[mi][ni][3]);
        }
}

// ============================================================
// prep: x -> normalized bf16 hi/lo AND fp16 hi/lo
// ============================================================
__global__ void prep_x_kernel(const float* __restrict__ x,
                              const float* __restrict__ g) {
    int row  = blockIdx.x * blockDim.y + threadIdx.y;
    int lane = threadIdx.x;
    const float4* xr = reinterpret_cast<const float4*>(x + (size_t)row * DD);
    float4 a = xr[lane];
    float4 b = xr[lane + 32];
    float s = a.x*a.x + a.y*a.y + a.z*a.z + a.w*a.w
            + b.x*b.x + b.y*b.y + b.z*b.z + b.w*b.w;
    #pragma unroll
    for (int off = 16; off; off >>= 1) s += __shfl_xor_sync(0xffffffffu, s, off);
    s = __shfl_sync(0xffffffffu, s, 0);
    float norm = sqrtf(s * (1.0f / DD));
    float scale = g[0] / fmaxf(norm, 1e-5f);

    float va[8] = {a.x, a.y, a.z, a.w, b.x, b.y, b.z, b.w};
    int idx[2] = {lane * 4, 128 + lane * 4};
    #pragma unroll
    for (int h = 0; h < 2; h++)
        #pragma unroll
        for (int j = 0; j < 4; j++) {
            float v = va[h*4 + j] * scale;
            size_t o = (size_t)row*DD + idx[h] + j;
            __nv_bfloat16 bhi, blo;
            bf16split(v, bhi, blo);
            d_xhi[o] = bhi; d_xlo[o] = blo;
            __half hhi, hlo;
            f16split(v, hhi, hlo);
            d_xh16[o] = hhi; d_xl16[o] = hlo;
        }
}

// ============================================================
// transpose W_uv: bf16 split + fp16 truncate in one pass
// ============================================================
__global__ void transpose_wuv_kernel(const float* __restrict__ in,
                                     int R, int C) {
    __shared__ float t[32][33];
    int c0 = blockIdx.x * 32, r0 = blockIdx.y * 32;
    int tx = threadIdx.x, ty = threadIdx.y;
    #pragma unroll
    for (int i = ty; i < 32; i += 8)
        t[i][tx] = in[(size_t)(r0 + i) * C + c0 + tx];
    __syncthreads();
    #pragma unroll
    for (int i = ty; i < 32; i += 8) {
        float val = t[tx][i];
        size_t idx = (size_t)(c0 + i) * R + r0 + tx;
        __nv_bfloat16 hi, lo;
        bf16split(val, hi, lo);
        d_wuvThi[idx] = hi;
        d_wuvTlo[idx] = lo;
        d_wuvTh16[idx] = __float2half_rn(val);
    }
}

// transpose + fp16 truncate (for v, W_o)
__global__ void transpose_half_kernel(const float* __restrict__ in,
                                      __half* __restrict__ outh,
                                      int R, int C) {
    __shared__ float t[32][33];
    size_t boff = (size_t)blockIdx.z * R * C;
    int c0 = blockIdx.x * 32, r0 = blockIdx.y * 32;
    int tx = threadIdx.x, ty = threadIdx.y;
    #pragma unroll
    for (int i = ty; i < 32; i += 8)
        t[i][tx] = in[boff + (size_t)(r0 + i) * C + c0 + tx];
    __syncthreads();
    #pragma unroll
    for (int i = ty; i < 32; i += 8) {
        size_t idx = boff + (size_t)(c0 + i) * R + r0 + tx;
        outh[idx] = __float2half_rn(t[tx][i]);
    }
}

// ============================================================
// Epilogues
// ============================================================
struct EpiUVFast {
    int rowBase, colBase;
    const float* buv;
    __device__ void operator()(int r, int c, float v0, float v1) const {
        int row = rowBase + r;
        float vv[2] = {v0, v1};
        #pragma unroll
        for (int i = 0; i < 2; i++) {
            int col = colBase + c + i;
            float val = vv[i] + buv[col];
            val = val / (1.0f + __expf(-val));
            if (col < HH) d_u[(size_t)row*HH + col] = val;
            else          d_v[(size_t)row*HH + (col - HH)] = val;
        }
    }
};

struct EpiQKGen {
    int rowBase, colBase;
    const float *buv, *gamma, *beta;
    __device__ void operator()(int r, int c, float v0, float v1) const {
        int row = rowBase + r;
        float vv[2] = {v0, v1};
        #pragma unroll
        for (int i = 0; i < 2; i++) {
            int s = colBase + c + i;
            float val = vv[i] + buv[2*HH + s];
            val = val / (1.0f + __expf(-val));
            float vq = val * gamma[s]      + beta[s];
            float vk = val * gamma[SS + s] + beta[SS + s];
            size_t qi = (size_t)row*SS + s;
            __nv_bfloat16 hi, lo;
            bf16split(vq, hi, lo); d_qhi[qi] = hi; d_qlo[qi] = lo;
            bf16split(vk, hi, lo); d_khi[qi] = hi; d_klo[qi] = lo;
        }
    }
};

struct EpiQK {
    size_t rowOff;   // b*NN + rowBase
    int colBase;
    __device__ void operator()(int r, int c, float v0, float v1) const {
        size_t idx = (rowOff + r) * NN + colBase + c;
        float a0 = fmaxf(v0 * RSQRT_S, 0.0f); a0 *= a0;
        float a1 = fmaxf(v1 * RSQRT_S, 0.0f); a1 *= a1;
        __half h0, l0, h1, l1;
        f16split(a0, h0, l0);
        f16split(a1, h1, l1);
        *reinterpret_cast<__half2*>(d_ahi + idx) = __halves2half2(h0, h1);
        *reinterpret_cast<__half2*>(d_alo + idx) = __halves2half2(l0, l1);
    }
};

struct EpiAV {
    size_t rowOff;   // b*NN + rowBase
    int colBase;
    __device__ void operator()(int r, int c, float v0, float v1) const {
        size_t rg = rowOff + r;
        size_t idx = rg * HH + colBase + c;
        float2 uu = *reinterpret_cast<const float2*>(d_u + idx);
        float g0 = uu.x * v0, g1 = uu.y * v1;
        __half h0, l0, h1, l1;
        f16split(g0, h0, l0);
        f16split(g1, h1, l1);
        *reinterpret_cast<__half2*>(d_ghi + idx) = __halves2half2(h0, h1);
        *reinterpret_cast<__half2*>(d_glo + idx) = __halves2half2(l0, l1);
    }
};

struct EpiO {
    int rowBase, colBase;
    const float* bo;
    float* out;
    __device__ void operator()(int r, int c, float v0, float v1) const {
        int row = rowBase + r;
        int col = colBase + c;
        float2 o = {v0 + bo[col], v1 + bo[col + 1]};
        *reinterpret_cast<float2*>(out + (size_t)row*DD + col) = o;
    }
};

// ============================================================
// GEMM kernels
// ============================================================
__global__ void __launch_bounds__(256, 2)
k_uv_fast(const float* __restrict__ buv) {
    extern __shared__ char smem[];
    int rowBase = blockIdx.y * 128, colBase = blockIdx.x * 128;
    EpiUVFast epi{rowBase, colBase, buv};
    core_f16(d_xh16 + (size_t)rowBase * DD, d_xl16 + (size_t)rowBase * DD, DD,
             d_wuvTh16 + (size_t)colBase * DD, DD,
             DD, smem, epi);
}

__global__ void __launch_bounds__(256, 2)
k_uv_qk(const float* __restrict__ buv, const float* __restrict__ gamma,
        const float* __restrict__ beta) {
    extern __shared__ char smem[];
    int rowBase = blockIdx.y * 128, colBase = blockIdx.x * 64;
    EpiQKGen epi{rowBase, colBase, buv, gamma, beta};
    core_bf16(d_xhi + (size_t)rowBase * DD, d_xlo + (size_t)rowBase * DD, DD,
              d_wuvThi + (size_t)(2*HH + colBase) * DD,
              d_wuvTlo + (size_t)(2*HH + colBase) * DD, DD,
              DD, smem, epi);
}

__global__ void __launch_bounds__(256, 2)
k_qk() {
    extern __shared__ char smem[];
    int b = blockIdx.z, rowBase = blockIdx.y * 128, colBase = blockIdx.x * 64;
    size_t ra = (size_t)b * NN + rowBase;
    size_t rb = (size_t)b * NN + colBase;
    EpiQK epi{ra, colBase};
    core_bf16(d_qhi + ra * SS, d_qlo + ra * SS, SS,
              d_khi + rb * SS, d_klo + rb * SS, SS,
              SS, smem, epi);
}

__global__ void __launch_bounds__(256, 2)
k_av() {
    extern __shared__ char smem[];
    int b = blockIdx.z, rowBase = blockIdx.y * 128, colBase = blockIdx.x * 128;
    size_t ra = (size_t)b * NN + rowBase;
    size_t hb = (size_t)b * HH + colBase;
    EpiAV epi{ra, colBase};
    core_f16(d_ahi + ra * NN, d_alo + ra * NN, NN,
             d_vT + hb * NN, NN,
             NN, smem, epi);
}

__global__ void __launch_bounds__(256, 2)
k_o(const float* __restrict__ bo, float* __restrict__ out) {
    extern __shared__ char smem[];
    int rowBase = blockIdx.y * 128, colBase = blockIdx.x * 128;
    EpiO epi{rowBase, colBase, bo, out};
    core_f16(d_ghi + (size_t)rowBase * HH, d_glo + (size_t)rowBase * HH, HH,
             d_woT + (size_t)colBase * HH, HH,
             HH, smem, epi);
}

// ============================================================
extern "C" void kernel_launch(void* const* d_in, const int* in_sizes, int n_in,
                              void* d_out, int out_size) {
    (void)in_sizes; (void)n_in; (void)out_size;
    const float* x     = (const float*)d_in[0];
    const float* g     = (const float*)d_in[1];
    const float* Wuv   = (const float*)d_in[2];
    const float* buv   = (const float*)d_in[3];
    const float* gamma = (const float*)d_in[4];
    const float* beta  = (const float*)d_in[5];
    const float* Wo    = (const float*)d_in[6];
    const float* bo    = (const float*)d_in[7];
    float* out = (float*)d_out;

    static int smem_set = 0;
    if (!smem_set) {
        cudaFuncSetAttribute(k_uv_fast, cudaFuncAttributeMaxDynamicSharedMemorySize, SMEM_B3);
        cudaFuncSetAttribute(k_uv_qk,   cudaFuncAttributeMaxDynamicSharedMemorySize, SMEM_B3);
        cudaFuncSetAttribute(k_qk,      cudaFuncAttributeMaxDynamicSharedMemorySize, SMEM_B3);
        cudaFuncSetAttribute(k_av,      cudaFuncAttributeMaxDynamicSharedMemorySize, SMEM_B3);
        cudaFuncSetAttribute(k_o,       cudaFuncAttributeMaxDynamicSharedMemorySize, SMEM_B3);
        smem_set = 1;
    }

    prep_x_kernel<<<BNROWS/8, dim3(32, 8)>>>(x, g);

    transpose_wuv_kernel<<<dim3(EE/32, DD/32, 1), dim3(32, 8)>>>(Wuv, DD, EE);
    {   // W_o: [H=512][D=256] -> [D][H] fp16
        __half* th;
        cudaGetSymbolAddress((void**)&th, d_woT);
        transpose_half_kernel<<<dim3(DD/32, HH/32, 1), dim3(32, 8)>>>(Wo, th, HH, DD);
    }

    k_uv_fast<<<dim3(2*HH/128, BNROWS/128), 256, SMEM_B3>>>(buv);
    k_uv_qk<<<dim3(SS/64, BNROWS/128), 256, SMEM_B3>>>(buv, gamma, beta);

    {   // v: per-batch [N=2048][H=512] -> [H][N] fp16
        float* vin;
        __half* th;
        cudaGetSymbolAddress((void**)&vin, d_v);
        cudaGetSymbolAddress((void**)&th, d_vT);
        transpose_half_kernel<<<dim3(HH/32, NN/32, BB), dim3(32, 8)>>>(vin, th, NN, HH);
    }

    k_qk<<<dim3(NN/64, NN/128, BB), 256, SMEM_B3>>>();
    k_av<<<dim3(HH/128, NN/128, BB), 256, SMEM_B3>>>();
    k_o<<<dim3(DD/128, BNROWS/128), 256, SMEM_B3>>>(bo, out);
}

// round 9
// speedup vs baseline: 1.8226x; 1.3632x over previous
#include <cuda_runtime.h>
#include <cuda_bf16.h>
#include <cuda_fp16.h>
#include <cstdint>
#include <math.h>

// Problem constants
#define BB 8
#define NN 2048
#define DD 256
#define SS 128
#define HH 512
#define EE 1152          // 2H + S
#define BNROWS (BB*NN)   // 16384
#define RSQRT_S 0.08838834764831845f  // 1/sqrt(128)

// ---- scratch (allocation-free rule: __device__ globals) ----
__device__ __nv_bfloat16 d_xhi[(size_t)BNROWS*DD];
__device__ __nv_bfloat16 d_xlo[(size_t)BNROWS*DD];
__device__ __half d_xh16[(size_t)BNROWS*DD];         // xn fp16 hi/lo (exact split)
__device__ __half d_xl16[(size_t)BNROWS*DD];
__device__ float d_u[(size_t)BNROWS*HH];
__device__ float d_v[(size_t)BNROWS*HH];
__device__ __nv_bfloat16 d_qhi[(size_t)BNROWS*SS];
__device__ __nv_bfloat16 d_qlo[(size_t)BNROWS*SS];
__device__ __nv_bfloat16 d_khi[(size_t)BNROWS*SS];
__device__ __nv_bfloat16 d_klo[(size_t)BNROWS*SS];
__device__ __half d_vT[(size_t)BB*HH*NN];            // [b][h][m] fp16 (truncated)
__device__ __half d_ahi[(size_t)BB*NN*NN];           // attn [b][n][m] fp16 (single)
__device__ __half d_ghi[(size_t)BNROWS*HH];          // gated fp16 (single)
__device__ __nv_bfloat16 d_wuvThi[(size_t)EE*DD];    // W_uv^T [e][d] bf16 hi/lo
__device__ __nv_bfloat16 d_wuvTlo[(size_t)EE*DD];
__device__ __half d_wuvTh16[(size_t)EE*DD];          // W_uv^T fp16 (truncated)
__device__ __half d_woT[(size_t)DD*HH];              // W_o^T [d][h] fp16 (truncated)

// ============================================================
// Helpers
// ============================================================
__device__ __forceinline__ uint32_t smem_u32(const void* p) {
    uint32_t a;
    asm("{ .reg .u64 t; cvta.to.shared.u64 t, %1; cvt.u32.u64 %0, t; }"
        : "=r"(a) : "l"(p));
    return a;
}

#define LDSM_X4(r0, r1, r2, r3, addr) \
    asm volatile("ldmatrix.sync.aligned.m8n8.x4.shared.b16 {%0,%1,%2,%3}, [%4];" \
        : "=r"(r0), "=r"(r1), "=r"(r2), "=r"(r3) : "r"(addr))

#define MMA_BF16(d, a, b) \
    asm volatile("mma.sync.aligned.m16n8k16.row.col.f32.bf16.bf16.f32 " \
        "{%0,%1,%2,%3}, {%4,%5,%6,%7}, {%8,%9}, {%0,%1,%2,%3};" \
        : "+f"((d)[0]), "+f"((d)[1]), "+f"((d)[2]), "+f"((d)[3]) \
        : "r"((a)[0]), "r"((a)[1]), "r"((a)[2]), "r"((a)[3]), \
          "r"((b)[0]), "r"((b)[1]))

#define MMA_F16(d, a, b) \
    asm volatile("mma.sync.aligned.m16n8k16.row.col.f32.f16.f16.f32 " \
        "{%0,%1,%2,%3}, {%4,%5,%6,%7}, {%8,%9}, {%0,%1,%2,%3};" \
        : "+f"((d)[0]), "+f"((d)[1]), "+f"((d)[2]), "+f"((d)[3]) \
        : "r"((a)[0]), "r"((a)[1]), "r"((a)[2]), "r"((a)[3]), \
          "r"((b)[0]), "r"((b)[1]))

__device__ __forceinline__ void cp16(uint32_t dst, const void* src) {
    asm volatile("cp.async.cg.shared.global [%0], [%1], 16;"
        :: "r"(dst), "l"(src));
}
#define CP_COMMIT() asm volatile("cp.async.commit_group;" ::: "memory")
#define CP_WAIT0()  asm volatile("cp.async.wait_group 0;" ::: "memory")

__device__ __forceinline__ void bf16split(float v, __nv_bfloat16& hi, __nv_bfloat16& lo) {
    hi = __float2bfloat16(v);
    lo = __float2bfloat16(v - __bfloat162float(hi));
}
__device__ __forceinline__ void f16split(float v, __half& hi, __half& lo) {
    hi = __float2half_rn(v);
    lo = __float2half_rn(v - __half2float(hi));
}

// 16B granule loader: ROWS*8 granules strided by 256 threads, 128B rows,
// swizzle gi ^= row&7.
template <int ROWS, class T>
__device__ __forceinline__ void load_oper(uint32_t dstBase, const T* src,
                                          int ld, int kt, int tid) {
    #pragma unroll
    for (int j = 0; j < ROWS*8/256; j++) {
        int g = tid + j * 256;
        int row = g >> 3;
        int gi  = g & 7;
        int gis = gi ^ (row & 7);
        cp16(dstBase + row * 128 + gis * 16, src + (size_t)row * ld + kt + gi * 8);
    }
}

// ============================================================
// bf16 3-term core: BM=128, BN=64, BK=64, 2 CTAs/SM.
// ============================================================
#define STAGE_B  49152
#define SMEM_B3  (2*STAGE_B)

__device__ __forceinline__ void load_chunk_b(uint32_t sb, int stage,
        const __nv_bfloat16* Ah, const __nv_bfloat16* Al, int ldA,
        const __nv_bfloat16* Bh, const __nv_bfloat16* Bl, int ldB,
        int kt, int tid) {
    uint32_t st = sb + stage * STAGE_B;
    load_oper<128>(st,         Ah, ldA, kt, tid);
    load_oper<128>(st + 16384, Al, ldA, kt, tid);
    load_oper<64> (st + 32768, Bh, ldB, kt, tid);
    load_oper<64> (st + 40960, Bl, ldB, kt, tid);
}

__device__ __forceinline__ void compute_chunk_b(uint32_t st, int lane, int wm, int wn,
                                                float acc[2][4][4]) {
    const uint32_t aH = st, aL = st + 16384, bH = st + 32768, bL = st + 40960;
    #pragma unroll
    for (int ks = 0; ks < 4; ks++) {
        uint32_t Ahf[2][4], Alf[2][4];
        #pragma unroll
        for (int mi = 0; mi < 2; mi++) {
            int row = wm * 32 + mi * 16 + (lane & 15);
            int gi  = ks * 2 + (lane >> 4);
            uint32_t off = row * 128 + ((gi ^ (row & 7)) * 16);
            LDSM_X4(Ahf[mi][0], Ahf[mi][1], Ahf[mi][2], Ahf[mi][3], aH + off);
            LDSM_X4(Alf[mi][0], Alf[mi][1], Alf[mi][2], Alf[mi][3], aL + off);
        }
        uint32_t Bhf[4][2], Blf[4][2];
        #pragma unroll
        for (int np = 0; np < 2; np++) {
            int row = wn * 32 + np * 16 + (lane & 7) + ((lane >> 4) << 3);
            int gi  = ks * 2 + ((lane >> 3) & 1);
            uint32_t off = row * 128 + ((gi ^ (row & 7)) * 16);
            LDSM_X4(Bhf[2*np][0], Bhf[2*np][1], Bhf[2*np+1][0], Bhf[2*np+1][1], bH + off);
            LDSM_X4(Blf[2*np][0], Blf[2*np][1], Blf[2*np+1][0], Blf[2*np+1][1], bL + off);
        }
        #pragma unroll
        for (int mi = 0; mi < 2; mi++)
            #pragma unroll
            for (int ni = 0; ni < 4; ni++) {
                MMA_BF16(acc[mi][ni], Ahf[mi], Bhf[ni]);
                MMA_BF16(acc[mi][ni], Ahf[mi], Blf[ni]);
                MMA_BF16(acc[mi][ni], Alf[mi], Bhf[ni]);
            }
    }
}

template <class Epi>
__device__ __forceinline__ void core_bf16(
        const __nv_bfloat16* Ah, const __nv_bfloat16* Al, int ldA,
        const __nv_bfloat16* Bh, const __nv_bfloat16* Bl, int ldB,
        int K, char* smem, Epi epi) {
    uint32_t sb = smem_u32(smem);
    int tid = threadIdx.x;
    int lane = tid & 31, warp = tid >> 5;
    int wm = warp & 3, wn = warp >> 2;

    float acc[2][4][4] = {};
    const int nc = K / 64;

    load_chunk_b(sb, 0, Ah, Al, ldA, Bh, Bl, ldB, 0, tid);
    CP_COMMIT();
    for (int c = 0; c < nc; c++) {
        CP_WAIT0();
        __syncthreads();
        if (c + 1 < nc) {
            load_chunk_b(sb, (c + 1) & 1, Ah, Al, ldA, Bh, Bl, ldB, (c + 1) * 64, tid);
            CP_COMMIT();
        }
        compute_chunk_b(sb + (c & 1) * STAGE_B, lane, wm, wn, acc);
    }

    #pragma unroll
    for (int mi = 0; mi < 2; mi++)
        #pragma unroll
        for (int ni = 0; ni < 4; ni++) {
            int r = wm * 32 + mi * 16 + (lane >> 2);
            int c = wn * 32 + ni * 8 + (lane & 3) * 2;
            epi(r,     c, acc[mi][ni][0], acc[mi][ni][1]);
            epi(r + 8, c, acc[mi][ni][2], acc[mi][ni][3]);
        }
}

// ============================================================
// fp16 2-term core: BM=128, BN=128, BK=64, 2 CTAs/SM.
// A fp16 hi/lo (exact split), B fp16 (truncated).
// ============================================================
__device__ __forceinline__ void load_chunk_h(uint32_t sb, int stage,
        const __half* Ah, const __half* Al, int ldA,
        const __half* Bh, int ldB, int kt, int tid) {
    uint32_t st = sb + stage * STAGE_B;
    load_oper<128>(st,         Ah, ldA, kt, tid);
    load_oper<128>(st + 16384, Al, ldA, kt, tid);
    load_oper<128>(st + 32768, Bh, ldB, kt, tid);
}

__device__ __forceinline__ void compute_chunk_h(uint32_t st, int lane, int wm, int wn,
                                                float acc[2][8][4]) {
    const uint32_t aH = st, aL = st + 16384, bH = st + 32768;
    #pragma unroll
    for (int ks = 0; ks < 4; ks++) {
        uint32_t Ahf[2][4], Alf[2][4];
        #pragma unroll
        for (int mi = 0; mi < 2; mi++) {
            int row = wm * 32 + mi * 16 + (lane & 15);
            int gi  = ks * 2 + (lane >> 4);
            uint32_t off = row * 128 + ((gi ^ (row & 7)) * 16);
            LDSM_X4(Ahf[mi][0], Ahf[mi][1], Ahf[mi][2], Ahf[mi][3], aH + off);
            LDSM_X4(Alf[mi][0], Alf[mi][1], Alf[mi][2], Alf[mi][3], aL + off);
        }
        uint32_t Bhf[8][2];
        #pragma unroll
        for (int np = 0; np < 4; np++) {
            int row = wn * 64 + np * 16 + (lane & 7) + ((lane >> 4) << 3);
            int gi  = ks * 2 + ((lane >> 3) & 1);
            uint32_t off = row * 128 + ((gi ^ (row & 7)) * 16);
            LDSM_X4(Bhf[2*np][0], Bhf[2*np][1], Bhf[2*np+1][0], Bhf[2*np+1][1], bH + off);
        }
        #pragma unroll
        for (int mi = 0; mi < 2; mi++)
            #pragma unroll
            for (int ni = 0; ni < 8; ni++) {
                MMA_F16(acc[mi][ni], Ahf[mi], Bhf[ni]);
                MMA_F16(acc[mi][ni], Alf[mi], Bhf[ni]);
            }
    }
}

template <class Epi>
__device__ __forceinline__ void core_f16(
        const __half* Ah, const __half* Al, int ldA,
        const __half* Bh, int ldB, int K, char* smem, Epi epi) {
    uint32_t sb = smem_u32(smem);
    int tid = threadIdx.x;
    int lane = tid & 31, warp = tid >> 5;
    int wm = warp & 3, wn = warp >> 2;

    float acc[2][8][4] = {};
    const int nc = K / 64;

    load_chunk_h(sb, 0, Ah, Al, ldA, Bh, ldB, 0, tid);
    CP_COMMIT();
    for (int c = 0; c < nc; c++) {
        CP_WAIT0();
        __syncthreads();
        if (c + 1 < nc) {
            load_chunk_h(sb, (c + 1) & 1, Ah, Al, ldA, Bh, ldB, (c + 1) * 64, tid);
            CP_COMMIT();
        }
        compute_chunk_h(sb + (c & 1) * STAGE_B, lane, wm, wn, acc);
    }

    #pragma unroll
    for (int mi = 0; mi < 2; mi++)
        #pragma unroll
        for (int ni = 0; ni < 8; ni++) {
            int r = wm * 32 + mi * 16 + (lane >> 2);
            int c = wn * 64 + ni * 8 + (lane & 3) * 2;
            epi(r,     c, acc[mi][ni][0], acc[mi][ni][1]);
            epi(r + 8, c, acc[mi][ni][2], acc[mi][ni][3]);
        }
}

// ============================================================
// fp16 single-term core: BM=128, BN=128, BK=64, 2 CTAs/SM.
// A fp16 (truncated), B fp16 (truncated).
// Stage = Ah 16K | Bh 16K = 32KB, 2 stages (64KB).
// ============================================================
#define STAGE_S  32768
#define SMEM_S1  (2*STAGE_S)

__device__ __forceinline__ void load_chunk_s(uint32_t sb, int stage,
        const __half* Ah, int ldA, const __half* Bh, int ldB, int kt, int tid) {
    uint32_t st = sb + stage * STAGE_S;
    load_oper<128>(st,         Ah, ldA, kt, tid);
    load_oper<128>(st + 16384, Bh, ldB, kt, tid);
}

__device__ __forceinline__ void compute_chunk_s(uint32_t st, int lane, int wm, int wn,
                                                float acc[2][8][4]) {
    const uint32_t aH = st, bH = st + 16384;
    #pragma unroll
    for (int ks = 0; ks < 4; ks++) {
        uint32_t Ahf[2][4];
        #pragma unroll
        for (int mi = 0; mi < 2; mi++) {
            int row = wm * 32 + mi * 16 + (lane & 15);
            int gi  = ks * 2 + (lane >> 4);
            uint32_t off = row * 128 + ((gi ^ (row & 7)) * 16);
            LDSM_X4(Ahf[mi][0], Ahf[mi][1], Ahf[mi][2], Ahf[mi][3], aH + off);
        }
        uint32_t Bhf[8][2];
        #pragma unroll
        for (int np = 0; np < 4; np++) {
            int row = wn * 64 + np * 16 + (lane & 7) + ((lane >> 4) << 3);
            int gi  = ks * 2 + ((lane >> 3) & 1);
            uint32_t off = row * 128 + ((gi ^ (row & 7)) * 16);
            LDSM_X4(Bhf[2*np][0], Bhf[2*np][1], Bhf[2*np+1][0], Bhf[2*np+1][1], bH + off);
        }
        #pragma unroll
        for (int mi = 0; mi < 2; mi++)
            #pragma unroll
            for (int ni = 0; ni < 8; ni++)
                MMA_F16(acc[mi][ni], Ahf[mi], Bhf[ni]);
    }
}

template <class Epi>
__device__ __forceinline__ void core_f16s(
        const __half* Ah, int ldA, const __half* Bh, int ldB,
        int K, char* smem, Epi epi) {
    uint32_t sb = smem_u32(smem);
    int tid = threadIdx.x;
    int lane = tid & 31, warp = tid >> 5;
    int wm = warp & 3, wn = warp >> 2;

    float acc[2][8][4] = {};
    const int nc = K / 64;

    load_chunk_s(sb, 0, Ah, ldA, Bh, ldB, 0, tid);
    CP_COMMIT();
    for (int c = 0; c < nc; c++) {
        CP_WAIT0();
        __syncthreads();
        if (c + 1 < nc) {
            load_chunk_s(sb, (c + 1) & 1, Ah, ldA, Bh, ldB, (c + 1) * 64, tid);
            CP_COMMIT();
        }
        compute_chunk_s(sb + (c & 1) * STAGE_S, lane, wm, wn, acc);
    }

    #pragma unroll
    for (int mi = 0; mi < 2; mi++)
        #pragma unroll
        for (int ni = 0; ni < 8; ni++) {
            int r = wm * 32 + mi * 16 + (lane >> 2);
            int c = wn * 64 + ni * 8 + (lane & 3) * 2;
            epi(r,     c, acc[mi][ni][0], acc[mi][ni][1]);
            epi(r + 8, c, acc[mi][ni][2], acc[mi][ni][3]);
        }
}

// ============================================================
// prep: x -> normalized bf16 hi/lo AND fp16 hi/lo
// ============================================================
__global__ void prep_x_kernel(const float* __restrict__ x,
                              const float* __restrict__ g) {
    int row  = blockIdx.x * blockDim.y + threadIdx.y;
    int lane = threadIdx.x;
    const float4* xr = reinterpret_cast<const float4*>(x + (size_t)row * DD);
    float4 a = xr[lane];
    float4 b = xr[lane + 32];
    float s = a.x*a.x + a.y*a.y + a.z*a.z + a.w*a.w
            + b.x*b.x + b.y*b.y + b.z*b.z + b.w*b.w;
    #pragma unroll
    for (int off = 16; off; off >>= 1) s += __shfl_xor_sync(0xffffffffu, s, off);
    s = __shfl_sync(0xffffffffu, s, 0);
    float norm = sqrtf(s * (1.0f / DD));
    float scale = g[0] / fmaxf(norm, 1e-5f);

    float va[8] = {a.x, a.y, a.z, a.w, b.x, b.y, b.z, b.w};
    int idx[2] = {lane * 4, 128 + lane * 4};
    #pragma unroll
    for (int h = 0; h < 2; h++)
        #pragma unroll
        for (int j = 0; j < 4; j++) {
            float v = va[h*4 + j] * scale;
            size_t o = (size_t)row*DD + idx[h] + j;
            __nv_bfloat16 bhi, blo;
            bf16split(v, bhi, blo);
            d_xhi[o] = bhi; d_xlo[o] = blo;
            __half hhi, hlo;
            f16split(v, hhi, hlo);
            d_xh16[o] = hhi; d_xl16[o] = hlo;
        }
}

// ============================================================
// transpose W_uv: bf16 split + fp16 truncate in one pass
// ============================================================
__global__ void transpose_wuv_kernel(const float* __restrict__ in,
                                     int R, int C) {
    __shared__ float t[32][33];
    int c0 = blockIdx.x * 32, r0 = blockIdx.y * 32;
    int tx = threadIdx.x, ty = threadIdx.y;
    #pragma unroll
    for (int i = ty; i < 32; i += 8)
        t[i][tx] = in[(size_t)(r0 + i) * C + c0 + tx];
    __syncthreads();
    #pragma unroll
    for (int i = ty; i < 32; i += 8) {
        float val = t[tx][i];
        size_t idx = (size_t)(c0 + i) * R + r0 + tx;
        __nv_bfloat16 hi, lo;
        bf16split(val, hi, lo);
        d_wuvThi[idx] = hi;
        d_wuvTlo[idx] = lo;
        d_wuvTh16[idx] = __float2half_rn(val);
    }
}

// transpose + fp16 truncate (for v, W_o)
__global__ void transpose_half_kernel(const float* __restrict__ in,
                                      __half* __restrict__ outh,
                                      int R, int C) {
    __shared__ float t[32][33];
    size_t boff = (size_t)blockIdx.z * R * C;
    int c0 = blockIdx.x * 32, r0 = blockIdx.y * 32;
    int tx = threadIdx.x, ty = threadIdx.y;
    #pragma unroll
    for (int i = ty; i < 32; i += 8)
        t[i][tx] = in[boff + (size_t)(r0 + i) * C + c0 + tx];
    __syncthreads();
    #pragma unroll
    for (int i = ty; i < 32; i += 8) {
        size_t idx = boff + (size_t)(c0 + i) * R + r0 + tx;
        outh[idx] = __float2half_rn(t[tx][i]);
    }
}

// ============================================================
// Epilogues
// ============================================================
struct EpiUVFast {
    int rowBase, colBase;
    const float* buv;
    __device__ void operator()(int r, int c, float v0, float v1) const {
        int row = rowBase + r;
        float vv[2] = {v0, v1};
        #pragma unroll
        for (int i = 0; i < 2; i++) {
            int col = colBase + c + i;
            float val = vv[i] + buv[col];
            val = val / (1.0f + __expf(-val));
            if (col < HH) d_u[(size_t)row*HH + col] = val;
            else          d_v[(size_t)row*HH + (col - HH)] = val;
        }
    }
};

struct EpiQKGen {
    int rowBase, colBase;
    const float *buv, *gamma, *beta;
    __device__ void operator()(int r, int c, float v0, float v1) const {
        int row = rowBase + r;
        float vv[2] = {v0, v1};
        #pragma unroll
        for (int i = 0; i < 2; i++) {
            int s = colBase + c + i;
            float val = vv[i] + buv[2*HH + s];
            val = val / (1.0f + __expf(-val));
            float vq = val * gamma[s]      + beta[s];
            float vk = val * gamma[SS + s] + beta[SS + s];
            size_t qi = (size_t)row*SS + s;
            __nv_bfloat16 hi, lo;
            bf16split(vq, hi, lo); d_qhi[qi] = hi; d_qlo[qi] = lo;
            bf16split(vk, hi, lo); d_khi[qi] = hi; d_klo[qi] = lo;
        }
    }
};

struct EpiQK {
    size_t rowOff;   // b*NN + rowBase
    int colBase;
    __device__ void operator()(int r, int c, float v0, float v1) const {
        size_t idx = (rowOff + r) * NN + colBase + c;
        float a0 = fmaxf(v0 * RSQRT_S, 0.0f); a0 *= a0;
        float a1 = fmaxf(v1 * RSQRT_S, 0.0f); a1 *= a1;
        *reinterpret_cast<__half2*>(d_ahi + idx) =
            __halves2half2(__float2half_rn(a0), __float2half_rn(a1));
    }
};

struct EpiAV {
    size_t rowOff;   // b*NN + rowBase
    int colBase;
    __device__ void operator()(int r, int c, float v0, float v1) const {
        size_t rg = rowOff + r;
        size_t idx = rg * HH + colBase + c;
        float2 uu = *reinterpret_cast<const float2*>(d_u + idx);
        float g0 = uu.x * v0, g1 = uu.y * v1;
        *reinterpret_cast<__half2*>(d_ghi + idx) =
            __halves2half2(__float2half_rn(g0), __float2half_rn(g1));
    }
};

struct EpiO {
    int rowBase, colBase;
    const float* bo;
    float* out;
    __device__ void operator()(int r, int c, float v0, float v1) const {
        int row = rowBase + r;
        int col = colBase + c;
        float2 o = {v0 + bo[col], v1 + bo[col + 1]};
        *reinterpret_cast<float2*>(out + (size_t)row*DD + col) = o;
    }
};

// ============================================================
// GEMM kernels
// ============================================================
__global__ void __launch_bounds__(256, 2)
k_uv_fast(const float* __restrict__ buv) {
    extern __shared__ char smem[];
    int rowBase = blockIdx.y * 128, colBase = blockIdx.x * 128;
    EpiUVFast epi{rowBase, colBase, buv};
    core_f16(d_xh16 + (size_t)rowBase * DD, d_xl16 + (size_t)rowBase * DD, DD,
             d_wuvTh16 + (size_t)colBase * DD, DD,
             DD, smem, epi);
}

__global__ void __launch_bounds__(256, 2)
k_uv_qk(const float* __restrict__ buv, const float* __restrict__ gamma,
        const float* __restrict__ beta) {
    extern __shared__ char smem[];
    int rowBase = blockIdx.y * 128, colBase = blockIdx.x * 64;
    EpiQKGen epi{rowBase, colBase, buv, gamma, beta};
    core_bf16(d_xhi + (size_t)rowBase * DD, d_xlo + (size_t)rowBase * DD, DD,
              d_wuvThi + (size_t)(2*HH + colBase) * DD,
              d_wuvTlo + (size_t)(2*HH + colBase) * DD, DD,
              DD, smem, epi);
}

__global__ void __launch_bounds__(256, 2)
k_qk() {
    extern __shared__ char smem[];
    int b = blockIdx.z, rowBase = blockIdx.y * 128, colBase = blockIdx.x * 64;
    size_t ra = (size_t)b * NN + rowBase;
    size_t rb = (size_t)b * NN + colBase;
    EpiQK epi{ra, colBase};
    core_bf16(d_qhi + ra * SS, d_qlo + ra * SS, SS,
              d_khi + rb * SS, d_klo + rb * SS, SS,
              SS, smem, epi);
}

__global__ void __launch_bounds__(256, 2)
k_av() {
    extern __shared__ char smem[];
    int b = blockIdx.z, rowBase = blockIdx.y * 128, colBase = blockIdx.x * 128;
    size_t ra = (size_t)b * NN + rowBase;
    size_t hb = (size_t)b * HH + colBase;
    EpiAV epi{ra, colBase};
    core_f16s(d_ahi + ra * NN, NN,
              d_vT + hb * NN, NN,
              NN, smem, epi);
}

__global__ void __launch_bounds__(256, 2)
k_o(const float* __restrict__ bo, float* __restrict__ out) {
    extern __shared__ char smem[];
    int rowBase = blockIdx.y * 128, colBase = blockIdx.x * 128;
    EpiO epi{rowBase, colBase, bo, out};
    core_f16s(d_ghi + (size_t)rowBase * HH, HH,
              d_woT + (size_t)colBase * HH, HH,
              HH, smem, epi);
}

// ============================================================
extern "C" void kernel_launch(void* const* d_in, const int* in_sizes, int n_in,
                              void* d_out, int out_size) {
    (void)in_sizes; (void)n_in; (void)out_size;
    const float* x     = (const float*)d_in[0];
    const float* g     = (const float*)d_in[1];
    const float* Wuv   = (const float*)d_in[2];
    const float* buv   = (const float*)d_in[3];
    const float* gamma = (const float*)d_in[4];
    const float* beta  = (const float*)d_in[5];
    const float* Wo    = (const float*)d_in[6];
    const float* bo    = (const float*)d_in[7];
    float* out = (float*)d_out;

    static int smem_set = 0;
    if (!smem_set) {
        cudaFuncSetAttribute(k_uv_fast, cudaFuncAttributeMaxDynamicSharedMemorySize, SMEM_B3);
        cudaFuncSetAttribute(k_uv_qk,   cudaFuncAttributeMaxDynamicSharedMemorySize, SMEM_B3);
        cudaFuncSetAttribute(k_qk,      cudaFuncAttributeMaxDynamicSharedMemorySize, SMEM_B3);
        cudaFuncSetAttribute(k_av,      cudaFuncAttributeMaxDynamicSharedMemorySize, SMEM_S1);
        cudaFuncSetAttribute(k_o,       cudaFuncAttributeMaxDynamicSharedMemorySize, SMEM_S1);
        smem_set = 1;
    }

    prep_x_kernel<<<BNROWS/8, dim3(32, 8)>>>(x, g);

    transpose_wuv_kernel<<<dim3(EE/32, DD/32, 1), dim3(32, 8)>>>(Wuv, DD, EE);
    {   // W_o: [H=512][D=256] -> [D][H] fp16
        __half* th;
        cudaGetSymbolAddress((void**)&th, d_woT);
        transpose_half_kernel<<<dim3(DD/32, HH/32, 1), dim3(32, 8)>>>(Wo, th, HH, DD);
    }

    k_uv_fast<<<dim3(2*HH/128, BNROWS/128), 256, SMEM_B3>>>(buv);
    k_uv_qk<<<dim3(SS/64, BNROWS/128), 256, SMEM_B3>>>(buv, gamma, beta);

    {   // v: per-batch [N=2048][H=512] -> [H][N] fp16
        float* vin;
        __half* th;
        cudaGetSymbolAddress((void**)&vin, d_v);
        cudaGetSymbolAddress((void**)&th, d_vT);
        transpose_half_kernel<<<dim3(HH/32, NN/32, BB), dim3(32, 8)>>>(vin, th, NN, HH);
    }

    k_qk<<<dim3(NN/64, NN/128, BB), 256, SMEM_B3>>>();
    k_av<<<dim3(HH/128, NN/128, BB), 256, SMEM_S1>>>();
    k_o<<<dim3(DD/128, BNROWS/128), 256, SMEM_S1>>>(bo, out);
}

// round 11
// speedup vs baseline: 2.0488x; 1.1241x over previous
#include <cuda_runtime.h>
#include <cuda_bf16.h>
#include <cuda_fp16.h>
#include <cstdint>
#include <math.h>

// Problem constants
#define BB 8
#define NN 2048
#define DD 256
#define SS 128
#define HH 512
#define EE 1152          // 2H + S
#define BNROWS (BB*NN)   // 16384
#define RSQRT_S 0.08838834764831845f  // 1/sqrt(128)

// ---- scratch (allocation-free rule: __device__ globals) ----
__device__ __nv_bfloat16 d_xhi[(size_t)BNROWS*DD];   // xn bf16 hi/lo (exact, for q/k gen)
__device__ __nv_bfloat16 d_xlo[(size_t)BNROWS*DD];
__device__ __half d_x16[(size_t)BNROWS*DD];          // xn fp16 (truncated, for u/v gen)
__device__ float d_u[(size_t)BNROWS*HH];
__device__ float d_v[(size_t)BNROWS*HH];
__device__ __half d_qh16[(size_t)BNROWS*SS];         // q fp16 hi/lo (exact split)
__device__ __half d_ql16[(size_t)BNROWS*SS];
__device__ __half d_k16[(size_t)BNROWS*SS];          // k fp16 (truncated)
__device__ __half d_vT[(size_t)BB*HH*NN];            // [b][h][m] fp16 (truncated)
__device__ __half d_ahi[(size_t)BB*NN*NN];           // attn [b][n][m] fp16 (single)
__device__ __half d_ghi[(size_t)BNROWS*HH];          // gated fp16 (single)
__device__ __nv_bfloat16 d_wuvThi[(size_t)EE*DD];    // W_uv^T [e][d] bf16 hi/lo
__device__ __nv_bfloat16 d_wuvTlo[(size_t)EE*DD];
__device__ __half d_wuvTh16[(size_t)EE*DD];          // W_uv^T fp16 (truncated)
__device__ __half d_woT[(size_t)DD*HH];              // W_o^T [d][h] fp16 (truncated)

// ============================================================
// Helpers
// ============================================================
__device__ __forceinline__ uint32_t smem_u32(const void* p) {
    uint32_t a;
    asm("{ .reg .u64 t; cvta.to.shared.u64 t, %1; cvt.u32.u64 %0, t; }"
        : "=r"(a) : "l"(p));
    return a;
}

#define LDSM_X4(r0, r1, r2, r3, addr) \
    asm volatile("ldmatrix.sync.aligned.m8n8.x4.shared.b16 {%0,%1,%2,%3}, [%4];" \
        : "=r"(r0), "=r"(r1), "=r"(r2), "=r"(r3) : "r"(addr))

#define MMA_BF16(d, a, b) \
    asm volatile("mma.sync.aligned.m16n8k16.row.col.f32.bf16.bf16.f32 " \
        "{%0,%1,%2,%3}, {%4,%5,%6,%7}, {%8,%9}, {%0,%1,%2,%3};" \
        : "+f"((d)[0]), "+f"((d)[1]), "+f"((d)[2]), "+f"((d)[3]) \
        : "r"((a)[0]), "r"((a)[1]), "r"((a)[2]), "r"((a)[3]), \
          "r"((b)[0]), "r"((b)[1]))

#define MMA_F16(d, a, b) \
    asm volatile("mma.sync.aligned.m16n8k16.row.col.f32.f16.f16.f32 " \
        "{%0,%1,%2,%3}, {%4,%5,%6,%7}, {%8,%9}, {%0,%1,%2,%3};" \
        : "+f"((d)[0]), "+f"((d)[1]), "+f"((d)[2]), "+f"((d)[3]) \
        : "r"((a)[0]), "r"((a)[1]), "r"((a)[2]), "r"((a)[3]), \
          "r"((b)[0]), "r"((b)[1]))

__device__ __forceinline__ void cp16(uint32_t dst, const void* src) {
    asm volatile("cp.async.cg.shared.global [%0], [%1], 16;"
        :: "r"(dst), "l"(src));
}
#define CP_COMMIT() asm volatile("cp.async.commit_group;" ::: "memory")
#define CP_WAIT0()  asm volatile("cp.async.wait_group 0;" ::: "memory")

__device__ __forceinline__ void bf16split(float v, __nv_bfloat16& hi, __nv_bfloat16& lo) {
    hi = __float2bfloat16(v);
    lo = __float2bfloat16(v - __bfloat162float(hi));
}
__device__ __forceinline__ void f16split(float v, __half& hi, __half& lo) {
    hi = __float2half_rn(v);
    lo = __float2half_rn(v - __half2float(hi));
}

// 16B granule loader: ROWS*8 granules strided by 256 threads, 128B rows,
// swizzle gi ^= row&7.
template <int ROWS, class T>
__device__ __forceinline__ void load_oper(uint32_t dstBase, const T* src,
                                          int ld, int kt, int tid) {
    #pragma unroll
    for (int j = 0; j < ROWS*8/256; j++) {
        int g = tid + j * 256;
        int row = g >> 3;
        int gi  = g & 7;
        int gis = gi ^ (row & 7);
        cp16(dstBase + row * 128 + gis * 16, src + (size_t)row * ld + kt + gi * 8);
    }
}

// ============================================================
// bf16 3-term core: BM=128, BN=64, BK=64, 2 CTAs/SM.
// (only used by k_uv_qk now — exact q/k generation)
// ============================================================
#define STAGE_B  49152
#define SMEM_B3  (2*STAGE_B)

__device__ __forceinline__ void load_chunk_b(uint32_t sb, int stage,
        const __nv_bfloat16* Ah, const __nv_bfloat16* Al, int ldA,
        const __nv_bfloat16* Bh, const __nv_bfloat16* Bl, int ldB,
        int kt, int tid) {
    uint32_t st = sb + stage * STAGE_B;
    load_oper<128>(st,         Ah, ldA, kt, tid);
    load_oper<128>(st + 16384, Al, ldA, kt, tid);
    load_oper<64> (st + 32768, Bh, ldB, kt, tid);
    load_oper<64> (st + 40960, Bl, ldB, kt, tid);
}

__device__ __forceinline__ void compute_chunk_b(uint32_t st, int lane, int wm, int wn,
                                                float acc[2][4][4]) {
    const uint32_t aH = st, aL = st + 16384, bH = st + 32768, bL = st + 40960;
    #pragma unroll
    for (int ks = 0; ks < 4; ks++) {
        uint32_t Ahf[2][4], Alf[2][4];
        #pragma unroll
        for (int mi = 0; mi < 2; mi++) {
            int row = wm * 32 + mi * 16 + (lane & 15);
            int gi  = ks * 2 + (lane >> 4);
            uint32_t off = row * 128 + ((gi ^ (row & 7)) * 16);
            LDSM_X4(Ahf[mi][0], Ahf[mi][1], Ahf[mi][2], Ahf[mi][3], aH + off);
            LDSM_X4(Alf[mi][0], Alf[mi][1], Alf[mi][2], Alf[mi][3], aL + off);
        }
        uint32_t Bhf[4][2], Blf[4][2];
        #pragma unroll
        for (int np = 0; np < 2; np++) {
            int row = wn * 32 + np * 16 + (lane & 7) + ((lane >> 4) << 3);
            int gi  = ks * 2 + ((lane >> 3) & 1);
            uint32_t off = row * 128 + ((gi ^ (row & 7)) * 16);
            LDSM_X4(Bhf[2*np][0], Bhf[2*np][1], Bhf[2*np+1][0], Bhf[2*np+1][1], bH + off);
            LDSM_X4(Blf[2*np][0], Blf[2*np][1], Blf[2*np+1][0], Blf[2*np+1][1], bL + off);
        }
        #pragma unroll
        for (int mi = 0; mi < 2; mi++)
            #pragma unroll
            for (int ni = 0; ni < 4; ni++) {
                MMA_BF16(acc[mi][ni], Ahf[mi], Bhf[ni]);
                MMA_BF16(acc[mi][ni], Ahf[mi], Blf[ni]);
                MMA_BF16(acc[mi][ni], Alf[mi], Bhf[ni]);
            }
    }
}

template <class Epi>
__device__ __forceinline__ void core_bf16(
        const __nv_bfloat16* Ah, const __nv_bfloat16* Al, int ldA,
        const __nv_bfloat16* Bh, const __nv_bfloat16* Bl, int ldB,
        int K, char* smem, Epi epi) {
    uint32_t sb = smem_u32(smem);
    int tid = threadIdx.x;
    int lane = tid & 31, warp = tid >> 5;
    int wm = warp & 3, wn = warp >> 2;

    float acc[2][4][4] = {};
    const int nc = K / 64;

    load_chunk_b(sb, 0, Ah, Al, ldA, Bh, Bl, ldB, 0, tid);
    CP_COMMIT();
    for (int c = 0; c < nc; c++) {
        CP_WAIT0();
        __syncthreads();
        if (c + 1 < nc) {
            load_chunk_b(sb, (c + 1) & 1, Ah, Al, ldA, Bh, Bl, ldB, (c + 1) * 64, tid);
            CP_COMMIT();
        }
        compute_chunk_b(sb + (c & 1) * STAGE_B, lane, wm, wn, acc);
    }

    #pragma unroll
    for (int mi = 0; mi < 2; mi++)
        #pragma unroll
        for (int ni = 0; ni < 4; ni++) {
            int r = wm * 32 + mi * 16 + (lane >> 2);
            int c = wn * 32 + ni * 8 + (lane & 3) * 2;
            epi(r,     c, acc[mi][ni][0], acc[mi][ni][1]);
            epi(r + 8, c, acc[mi][ni][2], acc[mi][ni][3]);
        }
}

// ============================================================
// fp16 2-term core: BM=128, BN=128, BK=64, 2 CTAs/SM.
// A fp16 hi/lo (exact split), B fp16 (truncated). (used by k_qk)
// ============================================================
__device__ __forceinline__ void load_chunk_h(uint32_t sb, int stage,
        const __half* Ah, const __half* Al, int ldA,
        const __half* Bh, int ldB, int kt, int tid) {
    uint32_t st = sb + stage * STAGE_B;
    load_oper<128>(st,         Ah, ldA, kt, tid);
    load_oper<128>(st + 16384, Al, ldA, kt, tid);
    load_oper<128>(st + 32768, Bh, ldB, kt, tid);
}

__device__ __forceinline__ void compute_chunk_h(uint32_t st, int lane, int wm, int wn,
                                                float acc[2][8][4]) {
    const uint32_t aH = st, aL = st + 16384, bH = st + 32768;
    #pragma unroll
    for (int ks = 0; ks < 4; ks++) {
        uint32_t Ahf[2][4], Alf[2][4];
        #pragma unroll
        for (int mi = 0; mi < 2; mi++) {
            int row = wm * 32 + mi * 16 + (lane & 15);
            int gi  = ks * 2 + (lane >> 4);
            uint32_t off = row * 128 + ((gi ^ (row & 7)) * 16);
            LDSM_X4(Ahf[mi][0], Ahf[mi][1], Ahf[mi][2], Ahf[mi][3], aH + off);
            LDSM_X4(Alf[mi][0], Alf[mi][1], Alf[mi][2], Alf[mi][3], aL + off);
        }
        uint32_t Bhf[8][2];
        #pragma unroll
        for (int np = 0; np < 4; np++) {
            int row = wn * 64 + np * 16 + (lane & 7) + ((lane >> 4) << 3);
            int gi  = ks * 2 + ((lane >> 3) & 1);
            uint32_t off = row * 128 + ((gi ^ (row & 7)) * 16);
            LDSM_X4(Bhf[2*np][0], Bhf[2*np][1], Bhf[2*np+1][0], Bhf[2*np+1][1], bH + off);
        }
        #pragma unroll
        for (int mi = 0; mi < 2; mi++)
            #pragma unroll
            for (int ni = 0; ni < 8; ni++) {
                MMA_F16(acc[mi][ni], Ahf[mi], Bhf[ni]);
                MMA_F16(acc[mi][ni], Alf[mi], Bhf[ni]);
            }
    }
}

template <class Epi>
__device__ __forceinline__ void core_f16(
        const __half* Ah, const __half* Al, int ldA,
        const __half* Bh, int ldB, int K, char* smem, Epi epi) {
    uint32_t sb = smem_u32(smem);
    int tid = threadIdx.x;
    int lane = tid & 31, warp = tid >> 5;
    int wm = warp & 3, wn = warp >> 2;

    float acc[2][8][4] = {};
    const int nc = K / 64;

    load_chunk_h(sb, 0, Ah, Al, ldA, Bh, ldB, 0, tid);
    CP_COMMIT();
    for (int c = 0; c < nc; c++) {
        CP_WAIT0();
        __syncthreads();
        if (c + 1 < nc) {
            load_chunk_h(sb, (c + 1) & 1, Ah, Al, ldA, Bh, ldB, (c + 1) * 64, tid);
            CP_COMMIT();
        }
        compute_chunk_h(sb + (c & 1) * STAGE_B, lane, wm, wn, acc);
    }

    #pragma unroll
    for (int mi = 0; mi < 2; mi++)
        #pragma unroll
        for (int ni = 0; ni < 8; ni++) {
            int r = wm * 32 + mi * 16 + (lane >> 2);
            int c = wn * 64 + ni * 8 + (lane & 3) * 2;
            epi(r,     c, acc[mi][ni][0], acc[mi][ni][1]);
            epi(r + 8, c, acc[mi][ni][2], acc[mi][ni][3]);
        }
}

// ============================================================
// fp16 single-term core: BM=128, BN=128, BK=64, 2 CTAs/SM.
// Stage = Ah 16K | Bh 16K = 32KB, 2 stages. (uv_fast, av, o)
// ============================================================
#define STAGE_S  32768
#define SMEM_S1  (2*STAGE_S)

__device__ __forceinline__ void load_chunk_s(uint32_t sb, int stage,
        const __half* Ah, int ldA, const __half* Bh, int ldB, int kt, int tid) {
    uint32_t st = sb + stage * STAGE_S;
    load_oper<128>(st,         Ah, ldA, kt, tid);
    load_oper<128>(st + 16384, Bh, ldB, kt, tid);
}

__device__ __forceinline__ void compute_chunk_s(uint32_t st, int lane, int wm, int wn,
                                                float acc[2][8][4]) {
    const uint32_t aH = st, bH = st + 16384;
    #pragma unroll
    for (int ks = 0; ks < 4; ks++) {
        uint32_t Ahf[2][4];
        #pragma unroll
        for (int mi = 0; mi < 2; mi++) {
            int row = wm * 32 + mi * 16 + (lane & 15);
            int gi  = ks * 2 + (lane >> 4);
            uint32_t off = row * 128 + ((gi ^ (row & 7)) * 16);
            LDSM_X4(Ahf[mi][0], Ahf[mi][1], Ahf[mi][2], Ahf[mi][3], aH + off);
        }
        uint32_t Bhf[8][2];
        #pragma unroll
        for (int np = 0; np < 4; np++) {
            int row = wn * 64 + np * 16 + (lane & 7) + ((lane >> 4) << 3);
            int gi  = ks * 2 + ((lane >> 3) & 1);
            uint32_t off = row * 128 + ((gi ^ (row & 7)) * 16);
            LDSM_X4(Bhf[2*np][0], Bhf[2*np][1], Bhf[2*np+1][0], Bhf[2*np+1][1], bH + off);
        }
        #pragma unroll
        for (int mi = 0; mi < 2; mi++)
            #pragma unroll
            for (int ni = 0; ni < 8; ni++)
                MMA_F16(acc[mi][ni], Ahf[mi], Bhf[ni]);
    }
}

template <class Epi>
__device__ __forceinline__ void core_f16s(
        const __half* Ah, int ldA, const __half* Bh, int ldB,
        int K, char* smem, Epi epi) {
    uint32_t sb = smem_u32(smem);
    int tid = threadIdx.x;
    int lane = tid & 31, warp = tid >> 5;
    int wm = warp & 3, wn = warp >> 2;

    float acc[2][8][4] = {};
    const int nc = K / 64;

    load_chunk_s(sb, 0, Ah, ldA, Bh, ldB, 0, tid);
    CP_COMMIT();
    for (int c = 0; c < nc; c++) {
        CP_WAIT0();
        __syncthreads();
        if (c + 1 < nc) {
            load_chunk_s(sb, (c + 1) & 1, Ah, ldA, Bh, ldB, (c + 1) * 64, tid);
            CP_COMMIT();
        }
        compute_chunk_s(sb + (c & 1) * STAGE_S, lane, wm, wn, acc);
    }

    #pragma unroll
    for (int mi = 0; mi < 2; mi++)
        #pragma unroll
        for (int ni = 0; ni < 8; ni++) {
            int r = wm * 32 + mi * 16 + (lane >> 2);
            int c = wn * 64 + ni * 8 + (lane & 3) * 2;
            epi(r,     c, acc[mi][ni][0], acc[mi][ni][1]);
            epi(r + 8, c, acc[mi][ni][2], acc[mi][ni][3]);
        }
}

// ============================================================
// prep: x -> normalized bf16 hi/lo AND fp16 (truncated)
// ============================================================
__global__ void prep_x_kernel(const float* __restrict__ x,
                              const float* __restrict__ g) {
    int row  = blockIdx.x * blockDim.y + threadIdx.y;
    int lane = threadIdx.x;
    const float4* xr = reinterpret_cast<const float4*>(x + (size_t)row * DD);
    float4 a = xr[lane];
    float4 b = xr[lane + 32];
    float s = a.x*a.x + a.y*a.y + a.z*a.z + a.w*a.w
            + b.x*b.x + b.y*b.y + b.z*b.z + b.w*b.w;
    #pragma unroll
    for (int off = 16; off; off >>= 1) s += __shfl_xor_sync(0xffffffffu, s, off);
    s = __shfl_sync(0xffffffffu, s, 0);
    float norm = sqrtf(s * (1.0f / DD));
    float scale = g[0] / fmaxf(norm, 1e-5f);

    float va[8] = {a.x, a.y, a.z, a.w, b.x, b.y, b.z, b.w};
    int idx[2] = {lane * 4, 128 + lane * 4};
    #pragma unroll
    for (int h = 0; h < 2; h++)
        #pragma unroll
        for (int j = 0; j < 4; j++) {
            float v = va[h*4 + j] * scale;
            size_t o = (size_t)row*DD + idx[h] + j;
            __nv_bfloat16 bhi, blo;
            bf16split(v, bhi, blo);
            d_xhi[o] = bhi; d_xlo[o] = blo;
            d_x16[o] = __float2half_rn(v);
        }
}

// ============================================================
// transpose W_uv: bf16 split + fp16 truncate in one pass
// ============================================================
__global__ void transpose_wuv_kernel(const float* __restrict__ in,
                                     int R, int C) {
    __shared__ float t[32][33];
    int c0 = blockIdx.x * 32, r0 = blockIdx.y * 32;
    int tx = threadIdx.x, ty = threadIdx.y;
    #pragma unroll
    for (int i = ty; i < 32; i += 8)
        t[i][tx] = in[(size_t)(r0 + i) * C + c0 + tx];
    __syncthreads();
    #pragma unroll
    for (int i = ty; i < 32; i += 8) {
        float val = t[tx][i];
        size_t idx = (size_t)(c0 + i) * R + r0 + tx;
        __nv_bfloat16 hi, lo;
        bf16split(val, hi, lo);
        d_wuvThi[idx] = hi;
        d_wuvTlo[idx] = lo;
        d_wuvTh16[idx] = __float2half_rn(val);
    }
}

// transpose + fp16 truncate (for v, W_o)
__global__ void transpose_half_kernel(const float* __restrict__ in,
                                      __half* __restrict__ outh,
                                      int R, int C) {
    __shared__ float t[32][33];
    size_t boff = (size_t)blockIdx.z * R * C;
    int c0 = blockIdx.x * 32, r0 = blockIdx.y * 32;
    int tx = threadIdx.x, ty = threadIdx.y;
    #pragma unroll
    for (int i = ty; i < 32; i += 8)
        t[i][tx] = in[boff + (size_t)(r0 + i) * C + c0 + tx];
    __syncthreads();
    #pragma unroll
    for (int i = ty; i < 32; i += 8) {
        size_t idx = boff + (size_t)(c0 + i) * R + r0 + tx;
        outh[idx] = __float2half_rn(t[tx][i]);
    }
}

// ============================================================
// Epilogues
// ============================================================
struct EpiUVFast {
    int rowBase, colBase;
    const float* buv;
    __device__ void operator()(int r, int c, float v0, float v1) const {
        int row = rowBase + r;
        float vv[2] = {v0, v1};
        #pragma unroll
        for (int i = 0; i < 2; i++) {
            int col = colBase + c + i;
            float val = vv[i] + buv[col];
            val = val / (1.0f + __expf(-val));
            if (col < HH) d_u[(size_t)row*HH + col] = val;
            else          d_v[(size_t)row*HH + (col - HH)] = val;
        }
    }
};

struct EpiQKGen {
    int rowBase, colBase;
    const float *buv, *gamma, *beta;
    __device__ void operator()(int r, int c, float v0, float v1) const {
        int row = rowBase + r;
        float vv[2] = {v0, v1};
        #pragma unroll
        for (int i = 0; i < 2; i++) {
            int s = colBase + c + i;
            float val = vv[i] + buv[2*HH + s];
            val = val / (1.0f + __expf(-val));
            float vq = val * gamma[s]      + beta[s];
            float vk = val * gamma[SS + s] + beta[SS + s];
            size_t qi = (size_t)row*SS + s;
            __half hi, lo;
            f16split(vq, hi, lo);
            d_qh16[qi] = hi; d_ql16[qi] = lo;
            d_k16[qi] = __float2half_rn(vk);
        }
    }
};

struct EpiQK {
    size_t rowOff;   // b*NN + rowBase
    int colBase;
    __device__ void operator()(int r, int c, float v0, float v1) const {
        size_t idx = (rowOff + r) * NN + colBase + c;
        float a0 = fmaxf(v0 * RSQRT_S, 0.0f); a0 *= a0;
        float a1 = fmaxf(v1 * RSQRT_S, 0.0f); a1 *= a1;
        *reinterpret_cast<__half2*>(d_ahi + idx) =
            __halves2half2(__float2half_rn(a0), __float2half_rn(a1));
    }
};

struct EpiAV {
    size_t rowOff;   // b*NN + rowBase
    int colBase;
    __device__ void operator()(int r, int c, float v0, float v1) const {
        size_t rg = rowOff + r;
        size_t idx = rg * HH + colBase + c;
        float2 uu = *reinterpret_cast<const float2*>(d_u + idx);
        float g0 = uu.x * v0, g1 = uu.y * v1;
        *reinterpret_cast<__half2*>(d_ghi + idx) =
            __halves2half2(__float2half_rn(g0), __float2half_rn(g1));
    }
};

struct EpiO {
    int rowBase, colBase;
    const float* bo;
    float* out;
    __device__ void operator()(int r, int c, float v0, float v1) const {
        int row = rowBase + r;
        int col = colBase + c;
        float2 o = {v0 + bo[col], v1 + bo[col + 1]};
        *reinterpret_cast<float2*>(out + (size_t)row*DD + col) = o;
    }
};

// ============================================================
// GEMM kernels
// ============================================================
// u/v columns: single-term fp16, BN=128
__global__ void __launch_bounds__(256, 2)
k_uv_fast(const float* __restrict__ buv) {
    extern __shared__ char smem[];
    int rowBase = blockIdx.y * 128, colBase = blockIdx.x * 128;
    EpiUVFast epi{rowBase, colBase, buv};
    core_f16s(d_x16 + (size_t)rowBase * DD, DD,
              d_wuvTh16 + (size_t)colBase * DD, DD,
              DD, smem, epi);
}

// q/k columns: exact bf16 3-term, BN=64
__global__ void __launch_bounds__(256, 2)
k_uv_qk(const float* __restrict__ buv, const float* __restrict__ gamma,
        const float* __restrict__ beta) {
    extern __shared__ char smem[];
    int rowBase = blockIdx.y * 128, colBase = blockIdx.x * 64;
    EpiQKGen epi{rowBase, colBase, buv, gamma, beta};
    core_bf16(d_xhi + (size_t)rowBase * DD, d_xlo + (size_t)rowBase * DD, DD,
              d_wuvThi + (size_t)(2*HH + colBase) * DD,
              d_wuvTlo + (size_t)(2*HH + colBase) * DD, DD,
              DD, smem, epi);
}

// qk: 2-term fp16, BN=128 (q exact hi/lo, k truncated)
__global__ void __launch_bounds__(256, 2)
k_qk() {
    extern __shared__ char smem[];
    int b = blockIdx.z, rowBase = blockIdx.y * 128, colBase = blockIdx.x * 128;
    size_t ra = (size_t)b * NN + rowBase;
    size_t rb = (size_t)b * NN + colBase;
    EpiQK epi{ra, colBase};
    core_f16(d_qh16 + ra * SS, d_ql16 + ra * SS, SS,
             d_k16 + rb * SS, SS,
             SS, smem, epi);
}

__global__ void __launch_bounds__(256, 2)
k_av() {
    extern __shared__ char smem[];
    int b = blockIdx.z, rowBase = blockIdx.y * 128, colBase = blockIdx.x * 128;
    size_t ra = (size_t)b * NN + rowBase;
    size_t hb = (size_t)b * HH + colBase;
    EpiAV epi{ra, colBase};
    core_f16s(d_ahi + ra * NN, NN,
              d_vT + hb * NN, NN,
              NN, smem, epi);
}

__global__ void __launch_bounds__(256, 2)
k_o(const float* __restrict__ bo, float* __restrict__ out) {
    extern __shared__ char smem[];
    int rowBase = blockIdx.y * 128, colBase = blockIdx.x * 128;
    EpiO epi{rowBase, colBase, bo, out};
    core_f16s(d_ghi + (size_t)rowBase * HH, HH,
              d_woT + (size_t)colBase * HH, HH,
              HH, smem, epi);
}

// ============================================================
extern "C" void kernel_launch(void* const* d_in, const int* in_sizes, int n_in,
                              void* d_out, int out_size) {
    (void)in_sizes; (void)n_in; (void)out_size;
    const float* x     = (const float*)d_in[0];
    const float* g     = (const float*)d_in[1];
    const float* Wuv   = (const float*)d_in[2];
    const float* buv   = (const float*)d_in[3];
    const float* gamma = (const float*)d_in[4];
    const float* beta  = (const float*)d_in[5];
    const float* Wo    = (const float*)d_in[6];
    const float* bo    = (const float*)d_in[7];
    float* out = (float*)d_out;

    static int smem_set = 0;
    if (!smem_set) {
        cudaFuncSetAttribute(k_uv_fast, cudaFuncAttributeMaxDynamicSharedMemorySize, SMEM_S1);
        cudaFuncSetAttribute(k_uv_qk,   cudaFuncAttributeMaxDynamicSharedMemorySize, SMEM_B3);
        cudaFuncSetAttribute(k_qk,      cudaFuncAttributeMaxDynamicSharedMemorySize, SMEM_B3);
        cudaFuncSetAttribute(k_av,      cudaFuncAttributeMaxDynamicSharedMemorySize, SMEM_S1);
        cudaFuncSetAttribute(k_o,       cudaFuncAttributeMaxDynamicSharedMemorySize, SMEM_S1);
        smem_set = 1;
    }

    prep_x_kernel<<<BNROWS/8, dim3(32, 8)>>>(x, g);

    transpose_wuv_kernel<<<dim3(EE/32, DD/32, 1), dim3(32, 8)>>>(Wuv, DD, EE);
    {   // W_o: [H=512][D=256] -> [D][H] fp16
        __half* th;
        cudaGetSymbolAddress((void**)&th, d_woT);
        transpose_half_kernel<<<dim3(DD/32, HH/32, 1), dim3(32, 8)>>>(Wo, th, HH, DD);
    }

    k_uv_fast<<<dim3(2*HH/128, BNROWS/128), 256, SMEM_S1>>>(buv);
    k_uv_qk<<<dim3(SS/64, BNROWS/128), 256, SMEM_B3>>>(buv, gamma, beta);

    {   // v: per-batch [N=2048][H=512] -> [H][N] fp16
        float* vin;
        __half* th;
        cudaGetSymbolAddress((void**)&vin, d_v);
        cudaGetSymbolAddress((void**)&th, d_vT);
        transpose_half_kernel<<<dim3(HH/32, NN/32, BB), dim3(32, 8)>>>(vin, th, NN, HH);
    }

    k_qk<<<dim3(NN/128, NN/128, BB), 256, SMEM_B3>>>();
    k_av<<<dim3(HH/128, NN/128, BB), 256, SMEM_S1>>>();
    k_o<<<dim3(DD/128, BNROWS/128), 256, SMEM_S1>>>(bo, out);
}

// round 12
// speedup vs baseline: 2.2717x; 1.1088x over previous
#include <cuda_runtime.h>
#include <cuda_fp16.h>
#include <cstdint>
#include <math.h>

// Problem constants
#define BB 8
#define NN 2048
#define DD 256
#define SS 128
#define HH 512
#define EE 1152          // 2H + S
#define BNROWS (BB*NN)   // 16384
#define RSQRT_S 0.08838834764831845f  // 1/sqrt(128)

// ---- scratch (allocation-free rule: __device__ globals) ----
__device__ __half d_xh16[(size_t)BNROWS*DD];         // xn fp16 hi (== truncated xn)
__device__ __half d_xl16[(size_t)BNROWS*DD];         // xn fp16 lo (exact split residual)
__device__ float d_u[(size_t)BNROWS*HH];
__device__ float d_v[(size_t)BNROWS*HH];
__device__ __half d_q16[(size_t)BNROWS*SS];          // q fp16 (truncated)
__device__ __half d_k16[(size_t)BNROWS*SS];          // k fp16 (truncated)
__device__ __half d_vT[(size_t)BB*HH*NN];            // [b][h][m] fp16
__device__ __half d_ahi[(size_t)BB*NN*NN];           // attn [b][n][m] fp16
__device__ __half d_ghi[(size_t)BNROWS*HH];          // gated fp16
__device__ __half d_wuvT16[(size_t)EE*DD];           // W_uv^T [e][d] fp16
__device__ __half d_woT[(size_t)DD*HH];              // W_o^T [d][h] fp16

// ============================================================
// Helpers
// ============================================================
__device__ __forceinline__ uint32_t smem_u32(const void* p) {
    uint32_t a;
    asm("{ .reg .u64 t; cvta.to.shared.u64 t, %1; cvt.u32.u64 %0, t; }"
        : "=r"(a) : "l"(p));
    return a;
}

#define LDSM_X4(r0, r1, r2, r3, addr) \
    asm volatile("ldmatrix.sync.aligned.m8n8.x4.shared.b16 {%0,%1,%2,%3}, [%4];" \
        : "=r"(r0), "=r"(r1), "=r"(r2), "=r"(r3) : "r"(addr))

#define MMA_F16(d, a, b) \
    asm volatile("mma.sync.aligned.m16n8k16.row.col.f32.f16.f16.f32 " \
        "{%0,%1,%2,%3}, {%4,%5,%6,%7}, {%8,%9}, {%0,%1,%2,%3};" \
        : "+f"((d)[0]), "+f"((d)[1]), "+f"((d)[2]), "+f"((d)[3]) \
        : "r"((a)[0]), "r"((a)[1]), "r"((a)[2]), "r"((a)[3]), \
          "r"((b)[0]), "r"((b)[1]))

__device__ __forceinline__ void cp16(uint32_t dst, const void* src) {
    asm volatile("cp.async.cg.shared.global [%0], [%1], 16;"
        :: "r"(dst), "l"(src));
}
#define CP_COMMIT() asm volatile("cp.async.commit_group;" ::: "memory")
#define CP_WAIT1()  asm volatile("cp.async.wait_group 1;" ::: "memory")
#define CP_WAIT0()  asm volatile("cp.async.wait_group 0;" ::: "memory")

__device__ __forceinline__ void f16split(float v, __half& hi, __half& lo) {
    hi = __float2half_rn(v);
    lo = __float2half_rn(v - __half2float(hi));
}

// 16B granule loader: ROWS*8 granules strided by 256 threads, 128B rows,
// swizzle gi ^= row&7.
template <int ROWS, class T>
__device__ __forceinline__ void load_oper(uint32_t dstBase, const T* src,
                                          int ld, int kt, int tid) {
    #pragma unroll
    for (int j = 0; j < ROWS*8/256; j++) {
        int g = tid + j * 256;
        int row = g >> 3;
        int gi  = g & 7;
        int gis = gi ^ (row & 7);
        cp16(dstBase + row * 128 + gis * 16, src + (size_t)row * ld + kt + gi * 8);
    }
}

// ============================================================
// fp16 2-term core: BM=128, BN=128, BK=64, 2-stage, 2 CTAs/SM.
// A fp16 hi/lo (exact split), B fp16 (truncated). (k_uv_qk only)
// Stage = Ah 16K | Al 16K | Bh 16K = 48KB.
// ============================================================
#define STAGE_B  49152
#define SMEM_B2  (2*STAGE_B)

__device__ __forceinline__ void load_chunk_h(uint32_t sb, int stage,
        const __half* Ah, const __half* Al, int ldA,
        const __half* Bh, int ldB, int kt, int tid) {
    uint32_t st = sb + stage * STAGE_B;
    load_oper<128>(st,         Ah, ldA, kt, tid);
    load_oper<128>(st + 16384, Al, ldA, kt, tid);
    load_oper<128>(st + 32768, Bh, ldB, kt, tid);
}

__device__ __forceinline__ void compute_chunk_h(uint32_t st, int lane, int wm, int wn,
                                                float acc[2][8][4]) {
    const uint32_t aH = st, aL = st + 16384, bH = st + 32768;
    #pragma unroll
    for (int ks = 0; ks < 4; ks++) {
        uint32_t Ahf[2][4], Alf[2][4];
        #pragma unroll
        for (int mi = 0; mi < 2; mi++) {
            int row = wm * 32 + mi * 16 + (lane & 15);
            int gi  = ks * 2 + (lane >> 4);
            uint32_t off = row * 128 + ((gi ^ (row & 7)) * 16);
            LDSM_X4(Ahf[mi][0], Ahf[mi][1], Ahf[mi][2], Ahf[mi][3], aH + off);
            LDSM_X4(Alf[mi][0], Alf[mi][1], Alf[mi][2], Alf[mi][3], aL + off);
        }
        uint32_t Bhf[8][2];
        #pragma unroll
        for (int np = 0; np < 4; np++) {
            int row = wn * 64 + np * 16 + (lane & 7) + ((lane >> 4) << 3);
            int gi  = ks * 2 + ((lane >> 3) & 1);
            uint32_t off = row * 128 + ((gi ^ (row & 7)) * 16);
            LDSM_X4(Bhf[2*np][0], Bhf[2*np][1], Bhf[2*np+1][0], Bhf[2*np+1][1], bH + off);
        }
        #pragma unroll
        for (int mi = 0; mi < 2; mi++)
            #pragma unroll
            for (int ni = 0; ni < 8; ni++) {
                MMA_F16(acc[mi][ni], Ahf[mi], Bhf[ni]);
                MMA_F16(acc[mi][ni], Alf[mi], Bhf[ni]);
            }
    }
}

template <class Epi>
__device__ __forceinline__ void core_f16(
        const __half* Ah, const __half* Al, int ldA,
        const __half* Bh, int ldB, int K, char* smem, Epi epi) {
    uint32_t sb = smem_u32(smem);
    int tid = threadIdx.x;
    int lane = tid & 31, warp = tid >> 5;
    int wm = warp & 3, wn = warp >> 2;

    float acc[2][8][4] = {};
    const int nc = K / 64;

    load_chunk_h(sb, 0, Ah, Al, ldA, Bh, ldB, 0, tid);
    CP_COMMIT();
    for (int c = 0; c < nc; c++) {
        CP_WAIT0();
        __syncthreads();
        if (c + 1 < nc) {
            load_chunk_h(sb, (c + 1) & 1, Ah, Al, ldA, Bh, ldB, (c + 1) * 64, tid);
            CP_COMMIT();
        }
        compute_chunk_h(sb + (c & 1) * STAGE_B, lane, wm, wn, acc);
    }

    #pragma unroll
    for (int mi = 0; mi < 2; mi++)
        #pragma unroll
        for (int ni = 0; ni < 8; ni++) {
            int r = wm * 32 + mi * 16 + (lane >> 2);
            int c = wn * 64 + ni * 8 + (lane & 3) * 2;
            epi(r,     c, acc[mi][ni][0], acc[mi][ni][1]);
            epi(r + 8, c, acc[mi][ni][2], acc[mi][ni][3]);
        }
}

// ============================================================
// fp16 single-term core: BM=128, BN=128, BK=64, 3-stage, 2 CTAs/SM.
// Stage = Ah 16K | Bh 16K = 32KB, 3 stages (96KB). wait_group 1.
// ============================================================
#define STAGE_S  32768
#define SMEM_S1  (3*STAGE_S)

__device__ __forceinline__ void load_chunk_s(uint32_t sb, int stage,
        const __half* Ah, int ldA, const __half* Bh, int ldB, int kt, int tid) {
    uint32_t st = sb + stage * STAGE_S;
    load_oper<128>(st,         Ah, ldA, kt, tid);
    load_oper<128>(st + 16384, Bh, ldB, kt, tid);
}

__device__ __forceinline__ void compute_chunk_s(uint32_t st, int lane, int wm, int wn,
                                                float acc[2][8][4]) {
    const uint32_t aH = st, bH = st + 16384;
    #pragma unroll
    for (int ks = 0; ks < 4; ks++) {
        uint32_t Ahf[2][4];
        #pragma unroll
        for (int mi = 0; mi < 2; mi++) {
            int row = wm * 32 + mi * 16 + (lane & 15);
            int gi  = ks * 2 + (lane >> 4);
            uint32_t off = row * 128 + ((gi ^ (row & 7)) * 16);
            LDSM_X4(Ahf[mi][0], Ahf[mi][1], Ahf[mi][2], Ahf[mi][3], aH + off);
        }
        uint32_t Bhf[8][2];
        #pragma unroll
        for (int np = 0; np < 4; np++) {
            int row = wn * 64 + np * 16 + (lane & 7) + ((lane >> 4) << 3);
            int gi  = ks * 2 + ((lane >> 3) & 1);
            uint32_t off = row * 128 + ((gi ^ (row & 7)) * 16);
            LDSM_X4(Bhf[2*np][0], Bhf[2*np][1], Bhf[2*np+1][0], Bhf[2*np+1][1], bH + off);
        }
        #pragma unroll
        for (int mi = 0; mi < 2; mi++)
            #pragma unroll
            for (int ni = 0; ni < 8; ni++)
                MMA_F16(acc[mi][ni], Ahf[mi], Bhf[ni]);
    }
}

template <class Epi>
__device__ __forceinline__ void core_f16s(
        const __half* Ah, int ldA, const __half* Bh, int ldB,
        int K, char* smem, Epi epi) {
    uint32_t sb = smem_u32(smem);
    int tid = threadIdx.x;
    int lane = tid & 31, warp = tid >> 5;
    int wm = warp & 3, wn = warp >> 2;

    float acc[2][8][4] = {};
    const int nc = K / 64;

    // prologue: chunks 0, 1
    load_chunk_s(sb, 0, Ah, ldA, Bh, ldB, 0, tid);
    CP_COMMIT();
    if (nc > 1) load_chunk_s(sb, 1, Ah, ldA, Bh, ldB, 64, tid);
    CP_COMMIT();

    for (int c = 0; c < nc; c++) {
        CP_WAIT1();          // chunk c resident; chunk c+1 may be in flight
        __syncthreads();     // all warps done computing chunk c-1
        if (c + 2 < nc) {
            int s = (c + 2) % 3;   // slot of chunk c-1 (safe after sync)
            load_chunk_s(sb, s, Ah, ldA, Bh, ldB, (c + 2) * 64, tid);
        }
        CP_COMMIT();
        compute_chunk_s(sb + (c % 3) * STAGE_S, lane, wm, wn, acc);
    }

    #pragma unroll
    for (int mi = 0; mi < 2; mi++)
        #pragma unroll
        for (int ni = 0; ni < 8; ni++) {
            int r = wm * 32 + mi * 16 + (lane >> 2);
            int c = wn * 64 + ni * 8 + (lane & 3) * 2;
            epi(r,     c, acc[mi][ni][0], acc[mi][ni][1]);
            epi(r + 8, c, acc[mi][ni][2], acc[mi][ni][3]);
        }
}

// ============================================================
// prep: x -> normalized fp16 hi/lo (exact split)
// ============================================================
__global__ void prep_x_kernel(const float* __restrict__ x,
                              const float* __restrict__ g) {
    int row  = blockIdx.x * blockDim.y + threadIdx.y;
    int lane = threadIdx.x;
    const float4* xr = reinterpret_cast<const float4*>(x + (size_t)row * DD);
    float4 a = xr[lane];
    float4 b = xr[lane + 32];
    float s = a.x*a.x + a.y*a.y + a.z*a.z + a.w*a.w
            + b.x*b.x + b.y*b.y + b.z*b.z + b.w*b.w;
    #pragma unroll
    for (int off = 16; off; off >>= 1) s += __shfl_xor_sync(0xffffffffu, s, off);
    s = __shfl_sync(0xffffffffu, s, 0);
    float norm = sqrtf(s * (1.0f / DD));
    float scale = g[0] / fmaxf(norm, 1e-5f);

    float va[8] = {a.x, a.y, a.z, a.w, b.x, b.y, b.z, b.w};
    int idx[2] = {lane * 4, 128 + lane * 4};
    #pragma unroll
    for (int h = 0; h < 2; h++)
        #pragma unroll
        for (int j = 0; j < 4; j++) {
            float v = va[h*4 + j] * scale;
            size_t o = (size_t)row*DD + idx[h] + j;
            __half hi, lo;
            f16split(v, hi, lo);
            d_xh16[o] = hi;
            d_xl16[o] = lo;
        }
}

// transpose + fp16 truncate (W_uv, W_o, v)
__global__ void transpose_half_kernel(const float* __restrict__ in,
                                      __half* __restrict__ outh,
                                      int R, int C) {
    __shared__ float t[32][33];
    size_t boff = (size_t)blockIdx.z * R * C;
    int c0 = blockIdx.x * 32, r0 = blockIdx.y * 32;
    int tx = threadIdx.x, ty = threadIdx.y;
    #pragma unroll
    for (int i = ty; i < 32; i += 8)
        t[i][tx] = in[boff + (size_t)(r0 + i) * C + c0 + tx];
    __syncthreads();
    #pragma unroll
    for (int i = ty; i < 32; i += 8) {
        size_t idx = boff + (size_t)(c0 + i) * R + r0 + tx;
        outh[idx] = __float2half_rn(t[tx][i]);
    }
}

// ============================================================
// Epilogues
// ============================================================
struct EpiUVFast {
    int rowBase, colBase;
    const float* buv;
    __device__ void operator()(int r, int c, float v0, float v1) const {
        int row = rowBase + r;
        float vv[2] = {v0, v1};
        #pragma unroll
        for (int i = 0; i < 2; i++) {
            int col = colBase + c + i;
            float val = vv[i] + buv[col];
            val = val / (1.0f + __expf(-val));
            if (col < HH) d_u[(size_t)row*HH + col] = val;
            else          d_v[(size_t)row*HH + (col - HH)] = val;
        }
    }
};

struct EpiQKGen {
    int rowBase;
    const float *buv, *gamma, *beta;
    __device__ void operator()(int r, int c, float v0, float v1) const {
        int row = rowBase + r;
        float vv[2] = {v0, v1};
        #pragma unroll
        for (int i = 0; i < 2; i++) {
            int s = c + i;   // colBase == 0, S == 128 tile
            float val = vv[i] + buv[2*HH + s];
            val = val / (1.0f + __expf(-val));
            float vq = val * gamma[s]      + beta[s];
            float vk = val * gamma[SS + s] + beta[SS + s];
            size_t qi = (size_t)row*SS + s;
            d_q16[qi] = __float2half_rn(vq);
            d_k16[qi] = __float2half_rn(vk);
        }
    }
};

struct EpiQK {
    size_t rowOff;   // b*NN + rowBase
    int colBase;
    __device__ void operator()(int r, int c, float v0, float v1) const {
        size_t idx = (rowOff + r) * NN + colBase + c;
        float a0 = fmaxf(v0 * RSQRT_S, 0.0f); a0 *= a0;
        float a1 = fmaxf(v1 * RSQRT_S, 0.0f); a1 *= a1;
        *reinterpret_cast<__half2*>(d_ahi + idx) =
            __halves2half2(__float2half_rn(a0), __float2half_rn(a1));
    }
};

struct EpiAV {
    size_t rowOff;   // b*NN + rowBase
    int colBase;
    __device__ void operator()(int r, int c, float v0, float v1) const {
        size_t rg = rowOff + r;
        size_t idx = rg * HH + colBase + c;
        float2 uu = *reinterpret_cast<const float2*>(d_u + idx);
        float g0 = uu.x * v0, g1 = uu.y * v1;
        *reinterpret_cast<__half2*>(d_ghi + idx) =
            __halves2half2(__float2half_rn(g0), __float2half_rn(g1));
    }
};

struct EpiO {
    int rowBase, colBase;
    const float* bo;
    float* out;
    __device__ void operator()(int r, int c, float v0, float v1) const {
        int row = rowBase + r;
        int col = colBase + c;
        float2 o = {v0 + bo[col], v1 + bo[col + 1]};
        *reinterpret_cast<float2*>(out + (size_t)row*DD + col) = o;
    }
};

// ============================================================
// GEMM kernels
// ============================================================
// u/v columns: single-term fp16, BN=128, 3-stage
__global__ void __launch_bounds__(256, 2)
k_uv_fast(const float* __restrict__ buv) {
    extern __shared__ char smem[];
    int rowBase = blockIdx.y * 128, colBase = blockIdx.x * 128;
    EpiUVFast epi{rowBase, colBase, buv};
    core_f16s(d_xh16 + (size_t)rowBase * DD, DD,
              d_wuvT16 + (size_t)colBase * DD, DD,
              DD, smem, epi);
}

// q/k columns: 2-term fp16 (xn exact hi/lo), BN=128 (exactly S cols)
__global__ void __launch_bounds__(256, 2)
k_uv_qk(const float* __restrict__ buv, const float* __restrict__ gamma,
        const float* __restrict__ beta) {
    extern __shared__ char smem[];
    int rowBase = blockIdx.y * 128;
    EpiQKGen epi{rowBase, buv, gamma, beta};
    core_f16(d_xh16 + (size_t)rowBase * DD, d_xl16 + (size_t)rowBase * DD, DD,
             d_wuvT16 + (size_t)(2*HH) * DD, DD,
             DD, smem, epi);
}

// qk: single-term fp16, BN=128, 3-stage
__global__ void __launch_bounds__(256, 2)
k_qk() {
    extern __shared__ char smem[];
    int b = blockIdx.z, rowBase = blockIdx.y * 128, colBase = blockIdx.x * 128;
    size_t ra = (size_t)b * NN + rowBase;
    size_t rb = (size_t)b * NN + colBase;
    EpiQK epi{ra, colBase};
    core_f16s(d_q16 + ra * SS, SS,
              d_k16 + rb * SS, SS,
              SS, smem, epi);
}

__global__ void __launch_bounds__(256, 2)
k_av() {
    extern __shared__ char smem[];
    int b = blockIdx.z, rowBase = blockIdx.y * 128, colBase = blockIdx.x * 128;
    size_t ra = (size_t)b * NN + rowBase;
    size_t hb = (size_t)b * HH + colBase;
    EpiAV epi{ra, colBase};
    core_f16s(d_ahi + ra * NN, NN,
              d_vT + hb * NN, NN,
              NN, smem, epi);
}

__global__ void __launch_bounds__(256, 2)
k_o(const float* __restrict__ bo, float* __restrict__ out) {
    extern __shared__ char smem[];
    int rowBase = blockIdx.y * 128, colBase = blockIdx.x * 128;
    EpiO epi{rowBase, colBase, bo, out};
    core_f16s(d_ghi + (size_t)rowBase * HH, HH,
              d_woT + (size_t)colBase * HH, HH,
              HH, smem, epi);
}

// ============================================================
extern "C" void kernel_launch(void* const* d_in, const int* in_sizes, int n_in,
                              void* d_out, int out_size) {
    (void)in_sizes; (void)n_in; (void)out_size;
    const float* x     = (const float*)d_in[0];
    const float* g     = (const float*)d_in[1];
    const float* Wuv   = (const float*)d_in[2];
    const float* buv   = (const float*)d_in[3];
    const float* gamma = (const float*)d_in[4];
    const float* beta  = (const float*)d_in[5];
    const float* Wo    = (const float*)d_in[6];
    const float* bo    = (const float*)d_in[7];
    float* out = (float*)d_out;

    static int smem_set = 0;
    if (!smem_set) {
        cudaFuncSetAttribute(k_uv_fast, cudaFuncAttributeMaxDynamicSharedMemorySize, SMEM_S1);
        cudaFuncSetAttribute(k_uv_qk,   cudaFuncAttributeMaxDynamicSharedMemorySize, SMEM_B2);
        cudaFuncSetAttribute(k_qk,      cudaFuncAttributeMaxDynamicSharedMemorySize, SMEM_S1);
        cudaFuncSetAttribute(k_av,      cudaFuncAttributeMaxDynamicSharedMemorySize, SMEM_S1);
        cudaFuncSetAttribute(k_o,       cudaFuncAttributeMaxDynamicSharedMemorySize, SMEM_S1);
        smem_set = 1;
    }

    prep_x_kernel<<<BNROWS/8, dim3(32, 8)>>>(x, g);

    {   // W_uv: [D=256][E=1152] -> [E][D] fp16
        __half* th;
        cudaGetSymbolAddress((void**)&th, d_wuvT16);
        transpose_half_kernel<<<dim3(EE/32, DD/32, 1), dim3(32, 8)>>>(Wuv, th, DD, EE);
    }
    {   // W_o: [H=512][D=256] -> [D][H] fp16
        __half* th;
        cudaGetSymbolAddress((void**)&th, d_woT);
        transpose_half_kernel<<<dim3(DD/32, HH/32, 1), dim3(32, 8)>>>(Wo, th, HH, DD);
    }

    k_uv_fast<<<dim3(2*HH/128, BNROWS/128), 256, SMEM_S1>>>(buv);
    k_uv_qk<<<dim3(1, BNROWS/128), 256, SMEM_B2>>>(buv, gamma, beta);

    {   // v: per-batch [N=2048][H=512] -> [H][N] fp16
        float* vin;
        __half* th;
        cudaGetSymbolAddress((void**)&vin, d_v);
        cudaGetSymbolAddress((void**)&th, d_vT);
        transpose_half_kernel<<<dim3(HH/32, NN/32, BB), dim3(32, 8)>>>(vin, th, NN, HH);
    }

    k_qk<<<dim3(NN/128, NN/128, BB), 256, SMEM_S1>>>();
    k_av<<<dim3(HH/128, NN/128, BB), 256, SMEM_S1>>>();
    k_o<<<dim3(DD/128, BNROWS/128), 256, SMEM_S1>>>(bo, out);
}

// round 13
// speedup vs baseline: 2.5150x; 1.1071x over previous
#include <cuda_runtime.h>
#include <cuda_fp16.h>
#include <cstdint>
#include <math.h>

// Problem constants
#define BB 8
#define NN 2048
#define DD 256
#define SS 128
#define HH 512
#define EE 1152          // 2H + S
#define BNROWS (BB*NN)   // 16384
#define RSQRT_S 0.08838834764831845f  // 1/sqrt(128)

// ---- scratch (allocation-free rule: __device__ globals) ----
__device__ __half d_x16[(size_t)BNROWS*DD];          // xn fp16 (truncated)
__device__ __half d_u16[(size_t)BNROWS*HH];          // u fp16
__device__ __half d_q16[(size_t)BNROWS*SS];          // q fp16
__device__ __half d_k16[(size_t)BNROWS*SS];          // k fp16
__device__ __half d_vT[(size_t)BB*HH*NN];            // [b][h][m] fp16 (written scattered)
__device__ __half d_ahi[(size_t)BB*NN*NN];           // attn [b][n][m] fp16
__device__ __half d_ghi[(size_t)BNROWS*HH];          // gated fp16
__device__ __half d_wuvT16[(size_t)EE*DD];           // W_uv^T [e][d] fp16
__device__ __half d_woT[(size_t)DD*HH];              // W_o^T [d][h] fp16

// ============================================================
// Helpers
// ============================================================
__device__ __forceinline__ uint32_t smem_u32(const void* p) {
    uint32_t a;
    asm("{ .reg .u64 t; cvta.to.shared.u64 t, %1; cvt.u32.u64 %0, t; }"
        : "=r"(a) : "l"(p));
    return a;
}

#define LDSM_X4(r0, r1, r2, r3, addr) \
    asm volatile("ldmatrix.sync.aligned.m8n8.x4.shared.b16 {%0,%1,%2,%3}, [%4];" \
        : "=r"(r0), "=r"(r1), "=r"(r2), "=r"(r3) : "r"(addr))

#define MMA_F16(d, a, b) \
    asm volatile("mma.sync.aligned.m16n8k16.row.col.f32.f16.f16.f32 " \
        "{%0,%1,%2,%3}, {%4,%5,%6,%7}, {%8,%9}, {%0,%1,%2,%3};" \
        : "+f"((d)[0]), "+f"((d)[1]), "+f"((d)[2]), "+f"((d)[3]) \
        : "r"((a)[0]), "r"((a)[1]), "r"((a)[2]), "r"((a)[3]), \
          "r"((b)[0]), "r"((b)[1]))

__device__ __forceinline__ void cp16(uint32_t dst, const void* src) {
    asm volatile("cp.async.cg.shared.global [%0], [%1], 16;"
        :: "r"(dst), "l"(src));
}
#define CP_COMMIT() asm volatile("cp.async.commit_group;" ::: "memory")
#define CP_WAIT1()  asm volatile("cp.async.wait_group 1;" ::: "memory")

// 16B granule loader: ROWS*8 granules strided by 256 threads, 128B rows,
// swizzle gi ^= row&7.
template <int ROWS, class T>
__device__ __forceinline__ void load_oper(uint32_t dstBase, const T* src,
                                          int ld, int kt, int tid) {
    #pragma unroll
    for (int j = 0; j < ROWS*8/256; j++) {
        int g = tid + j * 256;
        int row = g >> 3;
        int gi  = g & 7;
        int gis = gi ^ (row & 7);
        cp16(dstBase + row * 128 + gis * 16, src + (size_t)row * ld + kt + gi * 8);
    }
}

// ============================================================
// fp16 single-term core: BM=128, BN=128, BK=64, 3-stage, 2 CTAs/SM.
// Stage = Ah 16K | Bh 16K = 32KB, 3 stages (96KB). wait_group 1.
// ============================================================
#define STAGE_S  32768
#define SMEM_S1  (3*STAGE_S)

__device__ __forceinline__ void load_chunk_s(uint32_t sb, int stage,
        const __half* Ah, int ldA, const __half* Bh, int ldB, int kt, int tid) {
    uint32_t st = sb + stage * STAGE_S;
    load_oper<128>(st,         Ah, ldA, kt, tid);
    load_oper<128>(st + 16384, Bh, ldB, kt, tid);
}

__device__ __forceinline__ void compute_chunk_s(uint32_t st, int lane, int wm, int wn,
                                                float acc[2][8][4]) {
    const uint32_t aH = st, bH = st + 16384;
    #pragma unroll
    for (int ks = 0; ks < 4; ks++) {
        uint32_t Ahf[2][4];
        #pragma unroll
        for (int mi = 0; mi < 2; mi++) {
            int row = wm * 32 + mi * 16 + (lane & 15);
            int gi  = ks * 2 + (lane >> 4);
            uint32_t off = row * 128 + ((gi ^ (row & 7)) * 16);
            LDSM_X4(Ahf[mi][0], Ahf[mi][1], Ahf[mi][2], Ahf[mi][3], aH + off);
        }
        uint32_t Bhf[8][2];
        #pragma unroll
        for (int np = 0; np < 4; np++) {
            int row = wn * 64 + np * 16 + (lane & 7) + ((lane >> 4) << 3);
            int gi  = ks * 2 + ((lane >> 3) & 1);
            uint32_t off = row * 128 + ((gi ^ (row & 7)) * 16);
            LDSM_X4(Bhf[2*np][0], Bhf[2*np][1], Bhf[2*np+1][0], Bhf[2*np+1][1], bH + off);
        }
        #pragma unroll
        for (int mi = 0; mi < 2; mi++)
            #pragma unroll
            for (int ni = 0; ni < 8; ni++)
                MMA_F16(acc[mi][ni], Ahf[mi], Bhf[ni]);
    }
}

template <class Epi>
__device__ __forceinline__ void core_f16s(
        const __half* Ah, int ldA, const __half* Bh, int ldB,
        int K, char* smem, Epi epi) {
    uint32_t sb = smem_u32(smem);
    int tid = threadIdx.x;
    int lane = tid & 31, warp = tid >> 5;
    int wm = warp & 3, wn = warp >> 2;

    float acc[2][8][4] = {};
    const int nc = K / 64;

    // prologue: chunks 0, 1
    load_chunk_s(sb, 0, Ah, ldA, Bh, ldB, 0, tid);
    CP_COMMIT();
    if (nc > 1) load_chunk_s(sb, 1, Ah, ldA, Bh, ldB, 64, tid);
    CP_COMMIT();

    for (int c = 0; c < nc; c++) {
        CP_WAIT1();          // chunk c resident; chunk c+1 may be in flight
        __syncthreads();     // all warps done computing chunk c-1
        if (c + 2 < nc) {
            int s = (c + 2) % 3;   // slot of chunk c-1 (safe after sync)
            load_chunk_s(sb, s, Ah, ldA, Bh, ldB, (c + 2) * 64, tid);
        }
        CP_COMMIT();
        compute_chunk_s(sb + (c % 3) * STAGE_S, lane, wm, wn, acc);
    }

    #pragma unroll
    for (int mi = 0; mi < 2; mi++)
        #pragma unroll
        for (int ni = 0; ni < 8; ni++) {
            int r = wm * 32 + mi * 16 + (lane >> 2);
            int c = wn * 64 + ni * 8 + (lane & 3) * 2;
            epi(r,     c, acc[mi][ni][0], acc[mi][ni][1]);
            epi(r + 8, c, acc[mi][ni][2], acc[mi][ni][3]);
        }
}

// ============================================================
// prep: x -> normalized fp16 (truncated)
// ============================================================
__global__ void prep_x_kernel(const float* __restrict__ x,
                              const float* __restrict__ g) {
    int row  = blockIdx.x * blockDim.y + threadIdx.y;
    int lane = threadIdx.x;
    const float4* xr = reinterpret_cast<const float4*>(x + (size_t)row * DD);
    float4 a = xr[lane];
    float4 b = xr[lane + 32];
    float s = a.x*a.x + a.y*a.y + a.z*a.z + a.w*a.w
            + b.x*b.x + b.y*b.y + b.z*b.z + b.w*b.w;
    #pragma unroll
    for (int off = 16; off; off >>= 1) s += __shfl_xor_sync(0xffffffffu, s, off);
    s = __shfl_sync(0xffffffffu, s, 0);
    float norm = sqrtf(s * (1.0f / DD));
    float scale = g[0] / fmaxf(norm, 1e-5f);

    float va[8] = {a.x, a.y, a.z, a.w, b.x, b.y, b.z, b.w};
    int idx[2] = {lane * 4, 128 + lane * 4};
    #pragma unroll
    for (int h = 0; h < 2; h++)
        #pragma unroll
        for (int j = 0; j < 4; j++) {
            float v = va[h*4 + j] * scale;
            d_x16[(size_t)row*DD + idx[h] + j] = __float2half_rn(v);
        }
}

// transpose + fp16 truncate (W_uv, W_o)
__global__ void transpose_half_kernel(const float* __restrict__ in,
                                      __half* __restrict__ outh,
                                      int R, int C) {
    __shared__ float t[32][33];
    size_t boff = (size_t)blockIdx.z * R * C;
    int c0 = blockIdx.x * 32, r0 = blockIdx.y * 32;
    int tx = threadIdx.x, ty = threadIdx.y;
    #pragma unroll
    for (int i = ty; i < 32; i += 8)
        t[i][tx] = in[boff + (size_t)(r0 + i) * C + c0 + tx];
    __syncthreads();
    #pragma unroll
    for (int i = ty; i < 32; i += 8) {
        size_t idx = boff + (size_t)(c0 + i) * R + r0 + tx;
        outh[idx] = __float2half_rn(t[tx][i]);
    }
}

// ============================================================
// Epilogues
// ============================================================
// Full UV epilogue: cols [0,H)->u16, [H,2H)->vT scatter, [2H,E)->q/k
struct EpiUV {
    int rowBase, colBase;
    const float *buv, *gamma, *beta;
    __device__ void operator()(int r, int c, float v0, float v1) const {
        int row = rowBase + r;
        float s0 = v0 + buv[colBase + c];
        float s1 = v1 + buv[colBase + c + 1];
        s0 = s0 / (1.0f + __expf(-s0));
        s1 = s1 / (1.0f + __expf(-s1));
        if (colBase < HH) {
            *reinterpret_cast<__half2*>(d_u16 + (size_t)row*HH + colBase + c) =
                __halves2half2(__float2half_rn(s0), __float2half_rn(s1));
        } else if (colBase < 2*HH) {
            int b = row / NN, m = row % NN;
            int h = colBase + c - HH;
            size_t base = ((size_t)b*HH + h)*NN + m;
            d_vT[base]      = __float2half_rn(s0);
            d_vT[base + NN] = __float2half_rn(s1);
        } else {
            #pragma unroll
            for (int i = 0; i < 2; i++) {
                int s = colBase + c + i - 2*HH;
                float val = (i == 0) ? s0 : s1;
                float vq = val * gamma[s]      + beta[s];
                float vk = val * gamma[SS + s] + beta[SS + s];
                size_t qi = (size_t)row*SS + s;
                d_q16[qi] = __float2half_rn(vq);
                d_k16[qi] = __float2half_rn(vk);
            }
        }
    }
};

struct EpiQK {
    size_t rowOff;   // b*NN + rowBase
    int colBase;
    __device__ void operator()(int r, int c, float v0, float v1) const {
        size_t idx = (rowOff + r) * NN + colBase + c;
        float a0 = fmaxf(v0 * RSQRT_S, 0.0f); a0 *= a0;
        float a1 = fmaxf(v1 * RSQRT_S, 0.0f); a1 *= a1;
        *reinterpret_cast<__half2*>(d_ahi + idx) =
            __halves2half2(__float2half_rn(a0), __float2half_rn(a1));
    }
};

struct EpiAV {
    size_t rowOff;   // b*NN + rowBase
    int colBase;
    __device__ void operator()(int r, int c, float v0, float v1) const {
        size_t rg = rowOff + r;
        size_t idx = rg * HH + colBase + c;
        __half2 uu = *reinterpret_cast<const __half2*>(d_u16 + idx);
        float2 uf = __half22float2(uu);
        float g0 = uf.x * v0, g1 = uf.y * v1;
        *reinterpret_cast<__half2*>(d_ghi + idx) =
            __halves2half2(__float2half_rn(g0), __float2half_rn(g1));
    }
};

struct EpiO {
    int rowBase, colBase;
    const float* bo;
    float* out;
    __device__ void operator()(int r, int c, float v0, float v1) const {
        int row = rowBase + r;
        int col = colBase + c;
        float2 o = {v0 + bo[col], v1 + bo[col + 1]};
        *reinterpret_cast<float2*>(out + (size_t)row*DD + col) = o;
    }
};

// ============================================================
// GEMM kernels
// ============================================================
// full UV GEMM: single-term fp16, grid (E/128=9, BNROWS/128)
__global__ void __launch_bounds__(256, 2)
k_uv(const float* __restrict__ buv, const float* __restrict__ gamma,
     const float* __restrict__ beta) {
    extern __shared__ char smem[];
    int rowBase = blockIdx.y * 128, colBase = blockIdx.x * 128;
    EpiUV epi{rowBase, colBase, buv, gamma, beta};
    core_f16s(d_x16 + (size_t)rowBase * DD, DD,
              d_wuvT16 + (size_t)colBase * DD, DD,
              DD, smem, epi);
}

__global__ void __launch_bounds__(256, 2)
k_qk() {
    extern __shared__ char smem[];
    int b = blockIdx.z, rowBase = blockIdx.y * 128, colBase = blockIdx.x * 128;
    size_t ra = (size_t)b * NN + rowBase;
    size_t rb = (size_t)b * NN + colBase;
    EpiQK epi{ra, colBase};
    core_f16s(d_q16 + ra * SS, SS,
              d_k16 + rb * SS, SS,
              SS, smem, epi);
}

__global__ void __launch_bounds__(256, 2)
k_av() {
    extern __shared__ char smem[];
    int b = blockIdx.z, rowBase = blockIdx.y * 128, colBase = blockIdx.x * 128;
    size_t ra = (size_t)b * NN + rowBase;
    size_t hb = (size_t)b * HH + colBase;
    EpiAV epi{ra, colBase};
    core_f16s(d_ahi + ra * NN, NN,
              d_vT + hb * NN, NN,
              NN, smem, epi);
}

__global__ void __launch_bounds__(256, 2)
k_o(const float* __restrict__ bo, float* __restrict__ out) {
    extern __shared__ char smem[];
    int rowBase = blockIdx.y * 128, colBase = blockIdx.x * 128;
    EpiO epi{rowBase, colBase, bo, out};
    core_f16s(d_ghi + (size_t)rowBase * HH, HH,
              d_woT + (size_t)colBase * HH, HH,
              HH, smem, epi);
}

// ============================================================
extern "C" void kernel_launch(void* const* d_in, const int* in_sizes, int n_in,
                              void* d_out, int out_size) {
    (void)in_sizes; (void)n_in; (void)out_size;
    const float* x     = (const float*)d_in[0];
    const float* g     = (const float*)d_in[1];
    const float* Wuv   = (const float*)d_in[2];
    const float* buv   = (const float*)d_in[3];
    const float* gamma = (const float*)d_in[4];
    const float* beta  = (const float*)d_in[5];
    const float* Wo    = (const float*)d_in[6];
    const float* bo    = (const float*)d_in[7];
    float* out = (float*)d_out;

    static int smem_set = 0;
    if (!smem_set) {
        cudaFuncSetAttribute(k_uv, cudaFuncAttributeMaxDynamicSharedMemorySize, SMEM_S1);
        cudaFuncSetAttribute(k_qk, cudaFuncAttributeMaxDynamicSharedMemorySize, SMEM_S1);
        cudaFuncSetAttribute(k_av, cudaFuncAttributeMaxDynamicSharedMemorySize, SMEM_S1);
        cudaFuncSetAttribute(k_o,  cudaFuncAttributeMaxDynamicSharedMemorySize, SMEM_S1);
        smem_set = 1;
    }

    prep_x_kernel<<<BNROWS/8, dim3(32, 8)>>>(x, g);

    {   // W_uv: [D=256][E=1152] -> [E][D] fp16
        __half* th;
        cudaGetSymbolAddress((void**)&th, d_wuvT16);
        transpose_half_kernel<<<dim3(EE/32, DD/32, 1), dim3(32, 8)>>>(Wuv, th, DD, EE);
    }
    {   // W_o: [H=512][D=256] -> [D][H] fp16
        __half* th;
        cudaGetSymbolAddress((void**)&th, d_woT);
        transpose_half_kernel<<<dim3(DD/32, HH/32, 1), dim3(32, 8)>>>(Wo, th, HH, DD);
    }

    k_uv<<<dim3(EE/128, BNROWS/128), 256, SMEM_S1>>>(buv, gamma, beta);
    k_qk<<<dim3(NN/128, NN/128, BB), 256, SMEM_S1>>>();
    k_av<<<dim3(HH/128, NN/128, BB), 256, SMEM_S1>>>();
    k_o<<<dim3(DD/128, BNROWS/128), 256, SMEM_S1>>>(bo, out);
}